// round 13
// baseline (speedup 1.0000x reference)
#include <cuda_runtime.h>
#include <cuda_bf16.h>
#include <math.h>
#include <stdint.h>

#define B_ 8
#define C_ 192
#define H_ 128
#define W_ 128
#define HW_ 16384
#define HEADS_ 8
#define CPH_ 24
#define TEMP_INV 100.0f
#define EPS_ 1e-12f

#define NPIX_ (B_ * HW_)
#define NTILES_ (NPIX_ / 128)

// ---------------- scratch ----------------
__device__ float g_fus[(size_t)B_ * C_ * HW_];
__device__ __nv_bfloat16 g_o1b[(size_t)B_ * C_ * HW_];   // [y][x] bf16 (primary)
__device__ __nv_bfloat16 g_o2b[(size_t)B_ * C_ * HW_];
__device__ __nv_bfloat16 g_o1tb[(size_t)B_ * C_ * HW_];  // [x][y] bf16
__device__ __nv_bfloat16 g_o2tb[(size_t)B_ * C_ * HW_];
__device__ __nv_bfloat16 g_a1b[(size_t)B_ * HEADS_ * HW_];
__device__ __nv_bfloat16 g_a2b[(size_t)B_ * HEADS_ * HW_];
__device__ float g_n1h[B_ * HEADS_ * H_];   // squared sums (sqrt at consumer)
__device__ float g_n2h[B_ * HEADS_ * H_];
__device__ float g_n1w[B_ * HEADS_ * W_];
__device__ float g_n2w[B_ * HEADS_ * W_];

__device__ __forceinline__ float to_tf32(float x) {
    uint32_t u; asm("cvt.rna.tf32.f32 %0, %1;" : "=r"(u) : "f"(x));
    return __uint_as_float(u);
}
__device__ __forceinline__ float4 to_tf32_4(float4 v) {
    v.x = to_tf32(v.x); v.y = to_tf32(v.y); v.z = to_tf32(v.z); v.w = to_tf32(v.w);
    return v;
}
__device__ __forceinline__ uint32_t f2bf2(float a, float b) {
    __nv_bfloat162 h = __floats2bfloat162_rn(a, b);
    return *(uint32_t*)&h;
}

__device__ __forceinline__ void mma_tf32(float* c, const uint32_t* a, const uint32_t* b) {
    asm volatile(
        "mma.sync.aligned.m16n8k8.row.col.f32.tf32.tf32.f32 "
        "{%0,%1,%2,%3}, {%4,%5,%6,%7}, {%8,%9}, {%0,%1,%2,%3};"
        : "+f"(c[0]), "+f"(c[1]), "+f"(c[2]), "+f"(c[3])
        : "r"(a[0]), "r"(a[1]), "r"(a[2]), "r"(a[3]), "r"(b[0]), "r"(b[1]));
}
__device__ __forceinline__ void mma_bf16(float* c, const uint32_t* a, const uint32_t* b) {
    asm volatile(
        "mma.sync.aligned.m16n8k16.row.col.f32.bf16.bf16.f32 "
        "{%0,%1,%2,%3}, {%4,%5,%6,%7}, {%8,%9}, {%0,%1,%2,%3};"
        : "+f"(c[0]), "+f"(c[1]), "+f"(c[2]), "+f"(c[3])
        : "r"(a[0]), "r"(a[1]), "r"(a[2]), "r"(a[3]), "r"(b[0]), "r"(b[1]));
}

__device__ __forceinline__ void cpa16(uint32_t s, const void* g) {
    asm volatile("cp.async.cg.shared.global [%0], [%1], 16;" :: "r"(s), "l"(g));
}
#define CP_COMMIT() asm volatile("cp.async.commit_group;" ::: "memory")
#define CP_WAIT1()  asm volatile("cp.async.wait_group 1;" ::: "memory")
#define CP_WAIT0()  asm volatile("cp.async.wait_group 0;" ::: "memory")

// ---------------- repack (bf16 -> transposed bf16) + norms ----------------
__global__ __launch_bounds__(256) void repack_norm_kernel(
    const __nv_bfloat16* __restrict__ o1b, const __nv_bfloat16* __restrict__ o2b,
    __nv_bfloat16* __restrict__ o1tb, __nv_bfloat16* __restrict__ o2tb,
    float* __restrict__ n1h, float* __restrict__ n1w,
    float* __restrict__ n2h, float* __restrict__ n2w)
{
    __shared__ float t[32][33];
    __shared__ float cpart[8][32];
    const int cy = blockIdx.y;
    const int src = cy >= C_;
    const int c = src ? cy - C_ : cy;
    const int b = blockIdx.z;
    const int bh = b * 8 + c / CPH_;
    const int x0 = (blockIdx.x & 3) * 32, y0 = (blockIdx.x >> 2) * 32;
    const int tx = threadIdx.x, ty = threadIdx.y;
    const __nv_bfloat16* ib = (src ? o2b : o1b) + ((size_t)b * C_ + c) * HW_;
    __nv_bfloat16* obt = (src ? o2tb : o1tb) + ((size_t)b * C_ + c) * HW_;
    float* rowAcc = (src ? n2h : n1h);
    float* colAcc = (src ? n2w : n1w);

    float colLoc = 0.f;
#pragma unroll
    for (int ii = 0; ii < 4; ii++) {
        int i = ty + 8 * ii;
        float v = __bfloat162float(ib[(y0 + i) * 128 + x0 + tx]);
        t[i][tx] = v;
        float sq = v * v;
        colLoc += sq;
        float rs = sq;
#pragma unroll
        for (int s = 16; s >= 1; s >>= 1) rs += __shfl_xor_sync(0xffffffffu, rs, s);
        if (tx == 0) atomicAdd(&rowAcc[bh * 128 + y0 + i], rs);
    }
    cpart[ty][tx] = colLoc;
    __syncthreads();
#pragma unroll
    for (int i = ty; i < 32; i += 8)
        obt[(x0 + i) * 128 + y0 + tx] = __float2bfloat16_rn(t[tx][i]);
    if (ty == 0) {
        float s = cpart[0][tx] + cpart[1][tx] + cpart[2][tx] + cpart[3][tx]
                + cpart[4][tx] + cpart[5][tx] + cpart[6][tx] + cpart[7][tx];
        atomicAdd(&colAcc[bh * 128 + x0 + tx], s);
    }
}

__global__ void norm_init_kernel(float* a, float* b, float* c, float* d) {
    int i = blockIdx.x * 256 + threadIdx.x;
    if (i < B_ * HEADS_ * 128) { a[i] = 0.f; b[i] = 0.f; c[i] = 0.f; d[i] = 0.f; }
}

// ---------------- conv1x1 (channel-first fp32 in -> bf16 channel-first out) ----------------
#define SAS 36
#define ATS 136
#define CONV_ATBUF (32 * ATS)
#define CONV_WBUF (192 * SAS)
#define SMEM_BYTES ((2 * CONV_ATBUF + 2 * CONV_WBUF) * 4)

__global__ __launch_bounds__(512, 1) void conv_front_kernel(
    const float* __restrict__ x1, const float* __restrict__ x2,
    const float* __restrict__ Wt, const float* __restrict__ bias,
    __nv_bfloat16* __restrict__ o1b, __nv_bfloat16* __restrict__ o2b)
{
    extern __shared__ float sm[];
    const int tid = threadIdx.x;
    const int lane = tid & 31;
    const int g = lane >> 2;
    const int tig = lane & 3;
    const int wid = tid >> 5;
    const int mbase = (wid & 3) * 32;
    const int nbase = (wid >> 2) * 48;
    const int t = blockIdx.x;
    const int pg0 = t << 7;
    const int b = pg0 >> 14;
    const int p0 = pg0 & (HW_ - 1);
    const float* inb = (blockIdx.y ? x2 : x1) + (size_t)b * C_ * HW_;
    __nv_bfloat16* out = (blockIdx.y ? o2b : o1b);

    float c[2][6][4];
#pragma unroll
    for (int mt = 0; mt < 2; mt++)
#pragma unroll
        for (int nt = 0; nt < 6; nt++)
#pragma unroll
            for (int r = 0; r < 4; r++) c[mt][nt][r] = 0.f;

    float4 pa[2], pw[3];
#pragma unroll
    for (int r = 0; r < 2; r++) {
        int f = tid + 512 * r;
        pa[r] = *(const float4*)(inb + (size_t)(f >> 5) * HW_ + p0 + (f & 31) * 4);
    }
#pragma unroll
    for (int r = 0; r < 3; r++) {
        int f = tid + 512 * r;
        pw[r] = *(const float4*)(Wt + (size_t)(f >> 3) * C_ + (f & 7) * 4);
    }

    for (int kc = 0; kc < 6; kc++) {
        float* dA = sm + (kc & 1) * CONV_ATBUF;
        float* dW = sm + 2 * CONV_ATBUF + (kc & 1) * CONV_WBUF;
#pragma unroll
        for (int r = 0; r < 2; r++) {
            int f = tid + 512 * r;
            *(float4*)&dA[(f >> 5) * ATS + (f & 31) * 4] = to_tf32_4(pa[r]);
        }
#pragma unroll
        for (int r = 0; r < 3; r++) {
            int f = tid + 512 * r;
            *(float4*)&dW[(f >> 3) * SAS + (f & 7) * 4] = to_tf32_4(pw[r]);
        }
        __syncthreads();
        if (kc < 5) {
            int ko = (kc + 1) * 32;
#pragma unroll
            for (int r = 0; r < 2; r++) {
                int f = tid + 512 * r;
                pa[r] = *(const float4*)(inb + (size_t)(ko + (f >> 5)) * HW_ + p0 + (f & 31) * 4);
            }
#pragma unroll
            for (int r = 0; r < 3; r++) {
                int f = tid + 512 * r;
                pw[r] = *(const float4*)(Wt + (size_t)(f >> 3) * C_ + ko + (f & 7) * 4);
            }
        }
#pragma unroll
        for (int kk = 0; kk < 4; kk++) {
            const int k0 = kk * 8 + tig;
            uint32_t a[2][4], bb[6][2];
#pragma unroll
            for (int mt = 0; mt < 2; mt++) {
                int row = mbase + mt * 16 + g;
                a[mt][0] = __float_as_uint(dA[k0 * ATS + row]);
                a[mt][1] = __float_as_uint(dA[k0 * ATS + row + 8]);
                a[mt][2] = __float_as_uint(dA[(k0 + 4) * ATS + row]);
                a[mt][3] = __float_as_uint(dA[(k0 + 4) * ATS + row + 8]);
            }
#pragma unroll
            for (int nt = 0; nt < 6; nt++) {
                int col = nbase + nt * 8 + g;
                bb[nt][0] = __float_as_uint(dW[col * SAS + k0]);
                bb[nt][1] = __float_as_uint(dW[col * SAS + k0 + 4]);
            }
#pragma unroll
            for (int mt = 0; mt < 2; mt++)
#pragma unroll
                for (int nt = 0; nt < 6; nt++)
                    mma_tf32(c[mt][nt], a[mt], bb[nt]);
        }
    }

#pragma unroll
    for (int nt = 0; nt < 6; nt++) {
        int o = nbase + nt * 8 + 2 * tig;
        float bv0 = __ldg(&bias[o]);
        float bv1 = __ldg(&bias[o + 1]);
#pragma unroll
        for (int mt = 0; mt < 2; mt++)
#pragma unroll
            for (int half = 0; half < 2; half++) {
                int row = mbase + mt * 16 + g + half * 8;
#pragma unroll
                for (int cc = 0; cc < 2; cc++) {
                    float v = c[mt][nt][half * 2 + cc] + (cc ? bv1 : bv0);
                    out[((size_t)(b * C_ + o + cc) << 14) + p0 + row] = __float2bfloat16_rn(v);
                }
            }
    }
}

// ---------------- fused triple conv (fp32 fus in, fp32 out) ----------------
#define C3_SO_STRIDE 196
#define C3_SO_FLOATS (128 * C3_SO_STRIDE)
#define C3_W_OFF C3_SO_FLOATS
#define C3_SMEM_BYTES ((C3_SO_FLOATS + 2 * CONV_WBUF) * 4)

#define C3_MMALOOP_SO(kbase, dWpt, ACC) do {                                     \
    _Pragma("unroll")                                                            \
    for (int kk = 0; kk < 4; kk++) {                                             \
        const int k0 = kk * 8 + tig;                                             \
        uint32_t a[2][4], bb[6][2];                                              \
        _Pragma("unroll")                                                        \
        for (int mt = 0; mt < 2; mt++) {                                         \
            int row = mbase + mt * 16 + g;                                       \
            a[mt][0] = __float_as_uint(sO[row * C3_SO_STRIDE + (kbase) + k0]);   \
            a[mt][1] = __float_as_uint(sO[(row + 8) * C3_SO_STRIDE + (kbase) + k0]); \
            a[mt][2] = __float_as_uint(sO[row * C3_SO_STRIDE + (kbase) + k0 + 4]); \
            a[mt][3] = __float_as_uint(sO[(row + 8) * C3_SO_STRIDE + (kbase) + k0 + 4]); \
        }                                                                        \
        _Pragma("unroll")                                                        \
        for (int nt = 0; nt < 6; nt++) {                                         \
            int col = nbase + nt * 8 + g;                                        \
            bb[nt][0] = __float_as_uint((dWpt)[col * SAS + k0]);                 \
            bb[nt][1] = __float_as_uint((dWpt)[col * SAS + k0 + 4]);             \
        }                                                                        \
        _Pragma("unroll")                                                        \
        for (int mt = 0; mt < 2; mt++)                                           \
            _Pragma("unroll")                                                    \
            for (int nt = 0; nt < 6; nt++)                                       \
                mma_tf32(ACC[mt][nt], a[mt], bb[nt]);                            \
    }                                                                            \
} while (0)

#define C3_LOADW(Wsrc, ko) do {                                                  \
    _Pragma("unroll")                                                            \
    for (int r = 0; r < 3; r++) {                                                \
        int f = tid + 512 * r;                                                   \
        pw[r] = *(const float4*)((Wsrc) + (size_t)(f >> 3) * C_ + (ko) + (f & 7) * 4); \
    }                                                                            \
} while (0)

#define C3_STOREW(dWpt) do {                                                     \
    _Pragma("unroll")                                                            \
    for (int r = 0; r < 3; r++) {                                                \
        int f = tid + 512 * r;                                                   \
        *(float4*)&(dWpt)[(f >> 3) * SAS + (f & 7) * 4] = to_tf32_4(pw[r]);      \
    }                                                                            \
} while (0)

#define C3_ZEROACC(ACC) do {                                                     \
    _Pragma("unroll")                                                            \
    for (int mt = 0; mt < 2; mt++)                                               \
        _Pragma("unroll")                                                        \
        for (int nt = 0; nt < 6; nt++)                                           \
            _Pragma("unroll")                                                    \
            for (int r = 0; r < 4; r++) ACC[mt][nt][r] = 0.f;                    \
} while (0)

#define C3_EPI_SMEM(ACC, biasp, do_gelu) do {                                    \
    _Pragma("unroll")                                                            \
    for (int nt = 0; nt < 6; nt++) {                                             \
        int o = nbase + nt * 8 + 2 * tig;                                        \
        float bv0 = __ldg(&(biasp)[o]);                                          \
        float bv1 = __ldg(&(biasp)[o + 1]);                                      \
        _Pragma("unroll")                                                        \
        for (int mt = 0; mt < 2; mt++)                                           \
            _Pragma("unroll")                                                    \
            for (int half = 0; half < 2; half++) {                               \
                int row = mbase + mt * 16 + g + half * 8;                        \
                float v0 = ACC[mt][nt][half * 2 + 0] + bv0;                      \
                float v1 = ACC[mt][nt][half * 2 + 1] + bv1;                      \
                if (do_gelu) {                                                   \
                    v0 = 0.5f * v0 * (1.0f + erff(v0 * 0.70710678118654752f));   \
                    v1 = 0.5f * v1 * (1.0f + erff(v1 * 0.70710678118654752f));   \
                }                                                                \
                float2 w = {to_tf32(v0), to_tf32(v1)};                           \
                *(float2*)&sO[row * C3_SO_STRIDE + o] = w;                       \
            }                                                                    \
    }                                                                            \
} while (0)

__global__ __launch_bounds__(512, 1) void conv3x_kernel(
    const float* __restrict__ fus,
    const float* __restrict__ Wp,  const float* __restrict__ bp,
    const float* __restrict__ Wm1, const float* __restrict__ bm1,
    const float* __restrict__ Wm2, const float* __restrict__ bm2,
    const float* __restrict__ r1,  const float* __restrict__ r2,
    float* __restrict__ out)
{
    extern __shared__ float sm[];
    float* sO = sm;
    float* sW = sm + C3_W_OFF;
    const int tid = threadIdx.x;
    const int lane = tid & 31;
    const int g = lane >> 2;
    const int tig = lane & 3;
    const int wid = tid >> 5;
    const int mbase = (wid & 3) * 32;
    const int nbase = (wid >> 2) * 48;
    const int t = blockIdx.x;
    const int pg0 = t << 7;
    const int b = pg0 >> 14;
    const int p0 = pg0 & (HW_ - 1);
    const float* inb = fus + (size_t)b * C_ * HW_;

    float acc[2][6][4];
    float4 pa[2], pw[3];

    C3_ZEROACC(acc);
#pragma unroll
    for (int r = 0; r < 2; r++) {
        int f = tid + 512 * r;
        pa[r] = *(const float4*)(inb + (size_t)(f >> 5) * HW_ + p0 + (f & 31) * 4);
    }
    C3_LOADW(Wp, 0);
    for (int kc = 0; kc < 6; kc++) {
        float* dA = sm + (kc & 1) * CONV_ATBUF;
        float* dW = sW + (kc & 1) * CONV_WBUF;
#pragma unroll
        for (int r = 0; r < 2; r++) {
            int f = tid + 512 * r;
            *(float4*)&dA[(f >> 5) * ATS + (f & 31) * 4] = to_tf32_4(pa[r]);
        }
        C3_STOREW(dW);
        __syncthreads();
        if (kc < 5) {
            int ko = (kc + 1) * 32;
#pragma unroll
            for (int r = 0; r < 2; r++) {
                int f = tid + 512 * r;
                pa[r] = *(const float4*)(inb + (size_t)(ko + (f >> 5)) * HW_ + p0 + (f & 31) * 4);
            }
            C3_LOADW(Wp, ko);
        }
#pragma unroll
        for (int kk = 0; kk < 4; kk++) {
            const int k0 = kk * 8 + tig;
            uint32_t a[2][4], bb[6][2];
#pragma unroll
            for (int mt = 0; mt < 2; mt++) {
                int row = mbase + mt * 16 + g;
                a[mt][0] = __float_as_uint(dA[k0 * ATS + row]);
                a[mt][1] = __float_as_uint(dA[k0 * ATS + row + 8]);
                a[mt][2] = __float_as_uint(dA[(k0 + 4) * ATS + row]);
                a[mt][3] = __float_as_uint(dA[(k0 + 4) * ATS + row + 8]);
            }
#pragma unroll
            for (int nt = 0; nt < 6; nt++) {
                int col = nbase + nt * 8 + g;
                bb[nt][0] = __float_as_uint(dW[col * SAS + k0]);
                bb[nt][1] = __float_as_uint(dW[col * SAS + k0 + 4]);
            }
#pragma unroll
            for (int mt = 0; mt < 2; mt++)
#pragma unroll
                for (int nt = 0; nt < 6; nt++)
                    mma_tf32(acc[mt][nt], a[mt], bb[nt]);
        }
    }
    __syncthreads();
    C3_EPI_SMEM(acc, bp, 0);
    __syncthreads();

    C3_ZEROACC(acc);
    C3_LOADW(Wm1, 0);
    for (int kc = 0; kc < 6; kc++) {
        float* dW = sW + (kc & 1) * CONV_WBUF;
        C3_STOREW(dW);
        __syncthreads();
        if (kc < 5) C3_LOADW(Wm1, (kc + 1) * 32);
        C3_MMALOOP_SO(kc * 32, dW, acc);
    }
    __syncthreads();
    C3_EPI_SMEM(acc, bm1, 1);
    __syncthreads();

    C3_ZEROACC(acc);
    C3_LOADW(Wm2, 0);
    for (int kc = 0; kc < 6; kc++) {
        float* dW = sW + (kc & 1) * CONV_WBUF;
        C3_STOREW(dW);
        __syncthreads();
        if (kc < 5) C3_LOADW(Wm2, (kc + 1) * 32);
        C3_MMALOOP_SO(kc * 32, dW, acc);
    }

#pragma unroll
    for (int nt = 0; nt < 6; nt++) {
        int o = nbase + nt * 8 + 2 * tig;
        float bv0 = __ldg(&bm2[o]);
        float bv1 = __ldg(&bm2[o + 1]);
#pragma unroll
        for (int mt = 0; mt < 2; mt++)
#pragma unroll
            for (int half = 0; half < 2; half++) {
                int row = mbase + mt * 16 + g + half * 8;
#pragma unroll
                for (int cc = 0; cc < 2; cc++) {
                    float v = acc[mt][nt][half * 2 + cc] + (cc ? bv1 : bv0);
                    size_t idx = ((size_t)(b * C_ + o + cc) << 14) + p0 + row;
                    v += __ldg(&r1[idx]) + __ldg(&r2[idx]);
                    out[idx] = v;
                }
            }
    }
}

// ---------------- bf16 pipeline constants (attn/av, 256 thr, M-split 64) ----------------
#define BPAS 36
#define BAB_A (64 * BPAS)
#define BAB_B (128 * BPAS)
#define BPBUF (BAB_A + BAB_B)
#define BPIPE_SMEM_BYTES (2 * BPBUF * 4)

#define BPIPE_STAGE(sbuf32, Ap, Bp) do {                                         \
    _Pragma("unroll")                                                            \
    for (int r = 0; r < 2; r++) {                                                \
        int f = tid + 256 * r;                                                   \
        int row = f >> 3, c8 = f & 7;                                            \
        cpa16((sbuf32) + (row * BPAS + c8 * 4) * 4, (Ap) + row * 128 + c8 * 8);  \
    }                                                                            \
    _Pragma("unroll")                                                            \
    for (int r = 0; r < 4; r++) {                                                \
        int f = tid + 256 * r;                                                   \
        int row = f >> 3, c8 = f & 7;                                            \
        cpa16((sbuf32) + (BAB_A + row * BPAS + c8 * 4) * 4, (Bp) + row * 128 + c8 * 8); \
    }                                                                            \
    CP_COMMIT();                                                                 \
} while (0)

#define BPIPE_MMA(dA, dB, ACC) do {                                              \
    _Pragma("unroll")                                                            \
    for (int w = 0; w < 4; w++) {                                                \
        const int kp = w * 8 + tig;                                              \
        uint32_t a[2][4], bf[4][2];                                              \
        _Pragma("unroll")                                                        \
        for (int mt = 0; mt < 2; mt++) {                                         \
            int row = mbase + mt * 16 + g;                                       \
            a[mt][0] = (dA)[row * BPAS + kp];                                    \
            a[mt][1] = (dA)[(row + 8) * BPAS + kp];                              \
            a[mt][2] = (dA)[row * BPAS + kp + 4];                                \
            a[mt][3] = (dA)[(row + 8) * BPAS + kp + 4];                          \
        }                                                                        \
        _Pragma("unroll")                                                        \
        for (int nt = 0; nt < 4; nt++) {                                         \
            int col = nbase + nt * 8 + g;                                        \
            bf[nt][0] = (dB)[col * BPAS + kp];                                   \
            bf[nt][1] = (dB)[col * BPAS + kp + 4];                               \
        }                                                                        \
        _Pragma("unroll")                                                        \
        for (int mt = 0; mt < 2; mt++)                                           \
            _Pragma("unroll")                                                    \
            for (int nt = 0; nt < 4; nt++)                                       \
                mma_bf16(ACC[mt][nt], a[mt], bf[nt]);                            \
    }                                                                            \
} while (0)

// ---------------- attention: bf16 operands, fused softmax, bf16 output ----------------
__global__ __launch_bounds__(256, 2) void attn_mma_kernel(
    const __nv_bfloat16* __restrict__ o1b, const __nv_bfloat16* __restrict__ o2b,
    const __nv_bfloat16* __restrict__ o1tb, const __nv_bfloat16* __restrict__ o2tb,
    const float* __restrict__ n1h, const float* __restrict__ n2h,
    const float* __restrict__ n1w, const float* __restrict__ n2w,
    const float* __restrict__ pbh, const float* __restrict__ pbw,
    __nv_bfloat16* __restrict__ a1b, __nv_bfloat16* __restrict__ a2b)
{
    extern __shared__ float smf[];
    uint32_t* smu = (uint32_t*)smf;
    const uint32_t sbase = (uint32_t)__cvta_generic_to_shared(smf);
    const int bh = blockIdx.x;
    const int mode = blockIdx.y;
    const int mh = blockIdx.z;
    const int hd = bh & 7, b = bh >> 3;
    const int tid = threadIdx.x;
    const int lane = tid & 31, g = lane >> 2, tig = lane & 3;
    const int wid = tid >> 5;
    const int mbase = (wid & 1) * 32;
    const int nbase = (wid >> 1) * 32;
    const int mh64 = mh * 64;
    const __nv_bfloat16* Abase =
        ((mode ? o1tb : o2b) + ((size_t)b * C_ + hd * CPH_) * HW_) + mh64 * 128;
    const __nv_bfloat16* Bbase = (mode ? o2tb : o1b) + ((size_t)b * C_ + hd * CPH_) * HW_;

    float acc[2][4][4];
#pragma unroll
    for (int mt = 0; mt < 2; mt++)
#pragma unroll
        for (int nt = 0; nt < 4; nt++)
#pragma unroll
            for (int e = 0; e < 4; e++) acc[mt][nt][e] = 0.f;

    BPIPE_STAGE(sbase, Abase, Bbase);
    for (int kc = 0; kc < 48; kc++) {
        if (kc < 47) {
            int kn = kc + 1;
            const __nv_bfloat16* Ap = Abase + (kn >> 1) * HW_ + (kn & 1) * 64;
            const __nv_bfloat16* Bp = Bbase + (kn >> 1) * HW_ + (kn & 1) * 64;
            uint32_t sbuf = sbase + ((kn & 1) * BPBUF) * 4;
            BPIPE_STAGE(sbuf, Ap, Bp);
            CP_WAIT1();
        } else {
            CP_WAIT0();
        }
        __syncthreads();
        const uint32_t* dA = smu + (kc & 1) * BPBUF;
        const uint32_t* dB = dA + BAB_A;
        BPIPE_MMA(dA, dB, acc);
        __syncthreads();
    }

    const float* nI = mode ? n1w : n2h;
    const float* nJ = mode ? n2w : n1h;
    const float bias = mode ? __ldg(&pbw[hd]) : __ldg(&pbh[hd]);
    float rinv[4], cinv[8];
#pragma unroll
    for (int mt = 0; mt < 2; mt++)
#pragma unroll
        for (int half = 0; half < 2; half++) {
            int row = mbase + mt * 16 + g + half * 8;
            rinv[mt * 2 + half] =
                TEMP_INV / fmaxf(sqrtf(__ldg(&nI[bh * 128 + mh64 + row])), EPS_);
        }
#pragma unroll
    for (int nt = 0; nt < 4; nt++)
#pragma unroll
        for (int cc = 0; cc < 2; cc++) {
            int col = nbase + nt * 8 + 2 * tig + cc;
            cinv[nt * 2 + cc] = 1.f / fmaxf(sqrtf(__ldg(&nJ[bh * 128 + col])), EPS_);
        }
    float* sc = smf;
#pragma unroll
    for (int mt = 0; mt < 2; mt++)
#pragma unroll
        for (int half = 0; half < 2; half++) {
            int row = mbase + mt * 16 + g + half * 8;
            float ri = rinv[mt * 2 + half];
#pragma unroll
            for (int nt = 0; nt < 4; nt++) {
                int col = nbase + nt * 8 + 2 * tig;
                float2 v;
                v.x = acc[mt][nt][half * 2 + 0] * (ri * cinv[nt * 2 + 0]) + bias;
                v.y = acc[mt][nt][half * 2 + 1] * (ri * cinv[nt * 2 + 1]) + bias;
                *(float2*)&sc[row * 132 + col] = v;
            }
        }
    __syncthreads();

    __nv_bfloat16* outp = (mode ? a2b : a1b) + (size_t)bh * HW_ + mh64 * 128;
    for (int r = wid; r < 64; r += 8) {
        float4 v = *(float4*)&sc[r * 132 + lane * 4];
        float m = fmaxf(fmaxf(v.x, v.y), fmaxf(v.z, v.w));
#pragma unroll
        for (int s = 16; s >= 1; s >>= 1) m = fmaxf(m, __shfl_xor_sync(0xffffffffu, m, s));
        v.x = __expf(v.x - m); v.y = __expf(v.y - m);
        v.z = __expf(v.z - m); v.w = __expf(v.w - m);
        float su = v.x + v.y + v.z + v.w;
#pragma unroll
        for (int s = 16; s >= 1; s >>= 1) su += __shfl_xor_sync(0xffffffffu, su, s);
        float inv = 1.f / su;
        uint2 o;
        o.x = f2bf2(v.x * inv, v.y * inv);
        o.y = f2bf2(v.z * inv, v.w * inv);
        *(uint2*)&outp[r * 128 + lane * 4] = o;
    }
}

// ---------------- AV + q-residual + gated fusion: all-bf16 inputs ----------------
__global__ __launch_bounds__(256, 2) void av_mma_kernel(
    const __nv_bfloat16* __restrict__ o1b, const __nv_bfloat16* __restrict__ o2b,
    const __nv_bfloat16* __restrict__ o1tb,
    const __nv_bfloat16* __restrict__ a1b, const __nv_bfloat16* __restrict__ a2b,
    const float* __restrict__ n2h, const float* __restrict__ n1w,
    const float* __restrict__ gate, float* __restrict__ fus)
{
    extern __shared__ float smf[];
    uint32_t* smu = (uint32_t*)smf;
    const uint32_t sbase = (uint32_t)__cvta_generic_to_shared(smf);
    const int ch = blockIdx.x, b = blockIdx.y;
    const int mh = blockIdx.z;
    const int hd = ch / CPH_;
    const int bh = b * 8 + hd;
    const int tid = threadIdx.x;
    const int lane = tid & 31, g = lane >> 2, tig = lane & 3;
    const int wid = tid >> 5;
    const int mbase = (wid & 1) * 32;
    const int nbase = (wid >> 1) * 32;
    const int mh64 = mh * 64;

    const __nv_bfloat16* A1 = a1b + (size_t)bh * HW_ + mh64 * 128;
    const __nv_bfloat16* B1 = o1tb + ((size_t)b * C_ + ch) * HW_;
    const __nv_bfloat16* A2 = o2b + ((size_t)b * C_ + ch) * HW_ + mh64 * 128;
    const __nv_bfloat16* B2 = a2b + (size_t)bh * HW_;
    const __nv_bfloat16* S1 = o1b + ((size_t)b * C_ + ch) * HW_;
    const __nv_bfloat16* S2 = o2b + ((size_t)b * C_ + ch) * HW_;

    float acc1[2][4][4], acc2[2][4][4];
#pragma unroll
    for (int mt = 0; mt < 2; mt++)
#pragma unroll
        for (int nt = 0; nt < 4; nt++)
#pragma unroll
            for (int e = 0; e < 4; e++) { acc1[mt][nt][e] = 0.f; acc2[mt][nt][e] = 0.f; }

    const uint32_t sb0 = sbase;
    const uint32_t sb1 = sbase + BPBUF * 4;
    const uint32_t* dA0 = smu;
    const uint32_t* dB0 = smu + BAB_A;
    const uint32_t* dA1 = smu + BPBUF;
    const uint32_t* dB1 = smu + BPBUF + BAB_A;

    BPIPE_STAGE(sb0, A1, B1);
    BPIPE_STAGE(sb1, A1 + 64, B1 + 64);
    CP_WAIT1(); __syncthreads();
    BPIPE_MMA(dA0, dB0, acc1);
    __syncthreads();
    BPIPE_STAGE(sb0, A2, B2);
    CP_WAIT1(); __syncthreads();
    BPIPE_MMA(dA1, dB1, acc1);
    __syncthreads();
    BPIPE_STAGE(sb1, A2 + 64, B2 + 64);
    CP_WAIT1(); __syncthreads();
    BPIPE_MMA(dA0, dB0, acc2);
    CP_WAIT0(); __syncthreads();
    BPIPE_MMA(dA1, dB1, acc2);

    const float gg = 1.f / (1.f + expf(-__ldg(&gate[0])));
    float invy[4], invx[8];
#pragma unroll
    for (int mt = 0; mt < 2; mt++)
#pragma unroll
        for (int half = 0; half < 2; half++) {
            int row = mbase + mt * 16 + g + half * 8;
            invy[mt * 2 + half] =
                1.f / fmaxf(sqrtf(__ldg(&n2h[bh * 128 + mh64 + row])), EPS_);
        }
#pragma unroll
    for (int nt = 0; nt < 4; nt++)
#pragma unroll
        for (int cc = 0; cc < 2; cc++) {
            int col = nbase + nt * 8 + 2 * tig + cc;
            invx[nt * 2 + cc] = 1.f / fmaxf(sqrtf(__ldg(&n1w[bh * 128 + col])), EPS_);
        }

    float* fout = fus + ((size_t)b * C_ + ch) * HW_;
#pragma unroll
    for (int mt = 0; mt < 2; mt++)
#pragma unroll
        for (int half = 0; half < 2; half++) {
            int rl = mbase + mt * 16 + g + half * 8;
            int row = mh64 + rl;
            float iy = invy[mt * 2 + half];
#pragma unroll
            for (int nt = 0; nt < 4; nt++) {
                int col = nbase + nt * 8 + 2 * tig;
                float2 s1f = __bfloat1622float2(*(const __nv_bfloat162*)(S1 + row * 128 + col));
                float2 s2f = __bfloat1622float2(*(const __nv_bfloat162*)(S2 + row * 128 + col));
                float2 o;
                o.x = gg * (acc1[mt][nt][half * 2 + 0] + s2f.x * iy)
                    + (1.f - gg) * (acc2[mt][nt][half * 2 + 0] + s1f.x * invx[nt * 2 + 0]);
                o.y = gg * (acc1[mt][nt][half * 2 + 1] + s2f.y * iy)
                    + (1.f - gg) * (acc2[mt][nt][half * 2 + 1] + s1f.y * invx[nt * 2 + 1]);
                *(float2*)(fout + row * 128 + col) = o;
            }
        }
}

// ---------------- host launcher ----------------
extern "C" void kernel_launch(void* const* d_in, const int* in_sizes, int n_in,
                              void* d_out, int out_size)
{
    const float* x1  = (const float*)d_in[0];
    const float* x2  = (const float*)d_in[1];
    const float* Wp  = (const float*)d_in[2];
    const float* bp  = (const float*)d_in[3];
    const float* gate= (const float*)d_in[4];
    const float* pbh = (const float*)d_in[5];
    const float* pbw = (const float*)d_in[6];
    const float* Wm1 = (const float*)d_in[7];
    const float* bm1 = (const float*)d_in[8];
    const float* Wm2 = (const float*)d_in[9];
    const float* bm2 = (const float*)d_in[10];
    float* out = (float*)d_out;

    float *p_fus, *p_n1h, *p_n2h, *p_n1w, *p_n2w;
    __nv_bfloat16 *p_o1b, *p_o2b, *p_o1tb, *p_o2tb, *p_a1b, *p_a2b;
    cudaGetSymbolAddress((void**)&p_fus, g_fus);
    cudaGetSymbolAddress((void**)&p_o1b, g_o1b);
    cudaGetSymbolAddress((void**)&p_o2b, g_o2b);
    cudaGetSymbolAddress((void**)&p_o1tb, g_o1tb);
    cudaGetSymbolAddress((void**)&p_o2tb, g_o2tb);
    cudaGetSymbolAddress((void**)&p_a1b, g_a1b);
    cudaGetSymbolAddress((void**)&p_a2b, g_a2b);
    cudaGetSymbolAddress((void**)&p_n1h, g_n1h);
    cudaGetSymbolAddress((void**)&p_n2h, g_n2h);
    cudaGetSymbolAddress((void**)&p_n1w, g_n1w);
    cudaGetSymbolAddress((void**)&p_n2w, g_n2w);

    cudaFuncSetAttribute(conv_front_kernel, cudaFuncAttributeMaxDynamicSharedMemorySize, SMEM_BYTES);
    cudaFuncSetAttribute(conv3x_kernel, cudaFuncAttributeMaxDynamicSharedMemorySize, C3_SMEM_BYTES);
    cudaFuncSetAttribute(attn_mma_kernel, cudaFuncAttributeMaxDynamicSharedMemorySize, BPIPE_SMEM_BYTES);
    cudaFuncSetAttribute(av_mma_kernel, cudaFuncAttributeMaxDynamicSharedMemorySize, BPIPE_SMEM_BYTES);

    conv_front_kernel<<<dim3(NTILES_, 2), 512, SMEM_BYTES>>>(x1, x2, Wp, bp, p_o1b, p_o2b);

    norm_init_kernel<<<32, 256>>>(p_n1h, p_n1w, p_n2h, p_n2w);
    repack_norm_kernel<<<dim3(16, 2 * C_, B_), dim3(32, 8)>>>(
        p_o1b, p_o2b, p_o1tb, p_o2tb, p_n1h, p_n1w, p_n2h, p_n2w);

    attn_mma_kernel<<<dim3(B_ * HEADS_, 2, 2), 256, BPIPE_SMEM_BYTES>>>(
        p_o1b, p_o2b, p_o1tb, p_o2tb, p_n1h, p_n2h, p_n1w, p_n2w, pbh, pbw, p_a1b, p_a2b);

    av_mma_kernel<<<dim3(C_, B_, 2), 256, BPIPE_SMEM_BYTES>>>(
        p_o1b, p_o2b, p_o1tb, p_a1b, p_a2b, p_n2h, p_n1w, gate, p_fus);

    conv3x_kernel<<<NTILES_, 512, C3_SMEM_BYTES>>>(p_fus, Wp, bp, Wm1, bm1, Wm2, bm2,
                                                   x1, x2, out);

    (void)in_sizes; (void)n_in; (void)out_size;
}

// round 14
// speedup vs baseline: 1.4002x; 1.4002x over previous
#include <cuda_runtime.h>
#include <cuda_bf16.h>
#include <math.h>
#include <stdint.h>

#define B_ 8
#define C_ 192
#define H_ 128
#define W_ 128
#define HW_ 16384
#define HEADS_ 8
#define CPH_ 24
#define TEMP_INV 100.0f
#define EPS_ 1e-12f

#define NPIX_ (B_ * HW_)
#define NTILES_ (NPIX_ / 128)

// ---------------- scratch ----------------
__device__ float g_o1[(size_t)B_ * C_ * HW_];
__device__ float g_o2[(size_t)B_ * C_ * HW_];
__device__ float g_fus[(size_t)B_ * C_ * HW_];
__device__ __nv_bfloat16 g_o1b[(size_t)B_ * C_ * HW_];   // [y][x] bf16
__device__ __nv_bfloat16 g_o2b[(size_t)B_ * C_ * HW_];
__device__ __nv_bfloat16 g_o1tb[(size_t)B_ * C_ * HW_];  // [x][y] bf16
__device__ __nv_bfloat16 g_o2tb[(size_t)B_ * C_ * HW_];
__device__ __nv_bfloat16 g_a1b[(size_t)B_ * HEADS_ * HW_];
__device__ __nv_bfloat16 g_a2b[(size_t)B_ * HEADS_ * HW_];
__device__ float g_n1h[B_ * HEADS_ * H_];   // squared sums (sqrt at consumer)
__device__ float g_n2h[B_ * HEADS_ * H_];
__device__ float g_n1w[B_ * HEADS_ * W_];
__device__ float g_n2w[B_ * HEADS_ * W_];

__device__ __forceinline__ float to_tf32(float x) {
    uint32_t u; asm("cvt.rna.tf32.f32 %0, %1;" : "=r"(u) : "f"(x));
    return __uint_as_float(u);
}
__device__ __forceinline__ float4 to_tf32_4(float4 v) {
    v.x = to_tf32(v.x); v.y = to_tf32(v.y); v.z = to_tf32(v.z); v.w = to_tf32(v.w);
    return v;
}
__device__ __forceinline__ uint32_t f2bf2(float a, float b) {
    __nv_bfloat162 h = __floats2bfloat162_rn(a, b);
    return *(uint32_t*)&h;
}

__device__ __forceinline__ void mma_tf32(float* c, const uint32_t* a, const uint32_t* b) {
    asm volatile(
        "mma.sync.aligned.m16n8k8.row.col.f32.tf32.tf32.f32 "
        "{%0,%1,%2,%3}, {%4,%5,%6,%7}, {%8,%9}, {%0,%1,%2,%3};"
        : "+f"(c[0]), "+f"(c[1]), "+f"(c[2]), "+f"(c[3])
        : "r"(a[0]), "r"(a[1]), "r"(a[2]), "r"(a[3]), "r"(b[0]), "r"(b[1]));
}
__device__ __forceinline__ void mma_bf16(float* c, const uint32_t* a, const uint32_t* b) {
    asm volatile(
        "mma.sync.aligned.m16n8k16.row.col.f32.bf16.bf16.f32 "
        "{%0,%1,%2,%3}, {%4,%5,%6,%7}, {%8,%9}, {%0,%1,%2,%3};"
        : "+f"(c[0]), "+f"(c[1]), "+f"(c[2]), "+f"(c[3])
        : "r"(a[0]), "r"(a[1]), "r"(a[2]), "r"(a[3]), "r"(b[0]), "r"(b[1]));
}

__device__ __forceinline__ void cpa16(uint32_t s, const void* g) {
    asm volatile("cp.async.cg.shared.global [%0], [%1], 16;" :: "r"(s), "l"(g));
}
#define CP_COMMIT() asm volatile("cp.async.commit_group;" ::: "memory")
#define CP_WAIT1()  asm volatile("cp.async.wait_group 1;" ::: "memory")
#define CP_WAIT0()  asm volatile("cp.async.wait_group 0;" ::: "memory")

// ---------------- repack + norms + bf16 operand emission (fp32 in) ----------------
__global__ __launch_bounds__(256) void repack_norm_kernel(
    const float* __restrict__ o1, const float* __restrict__ o2,
    __nv_bfloat16* __restrict__ o1b, __nv_bfloat16* __restrict__ o2b,
    __nv_bfloat16* __restrict__ o1tb, __nv_bfloat16* __restrict__ o2tb,
    float* __restrict__ n1h, float* __restrict__ n1w,
    float* __restrict__ n2h, float* __restrict__ n2w)
{
    __shared__ float t[32][33];
    __shared__ float cpart[8][32];
    const int cy = blockIdx.y;
    const int src = cy >= C_;
    const int c = src ? cy - C_ : cy;
    const int b = blockIdx.z;
    const int bh = b * 8 + c / CPH_;
    const int x0 = (blockIdx.x & 3) * 32, y0 = (blockIdx.x >> 2) * 32;
    const int tx = threadIdx.x, ty = threadIdx.y;
    const float* ib = (src ? o2 : o1) + ((size_t)b * C_ + c) * HW_;
    __nv_bfloat16* obr = (src ? o2b : o1b) + ((size_t)b * C_ + c) * HW_;
    __nv_bfloat16* obt = (src ? o2tb : o1tb) + ((size_t)b * C_ + c) * HW_;
    float* rowAcc = (src ? n2h : n1h);
    float* colAcc = (src ? n2w : n1w);

    float colLoc = 0.f;
#pragma unroll
    for (int ii = 0; ii < 4; ii++) {
        int i = ty + 8 * ii;
        float v = ib[(y0 + i) * 128 + x0 + tx];
        t[i][tx] = v;
        obr[(y0 + i) * 128 + x0 + tx] = __float2bfloat16_rn(v);
        float sq = v * v;
        colLoc += sq;
        float rs = sq;
#pragma unroll
        for (int s = 16; s >= 1; s >>= 1) rs += __shfl_xor_sync(0xffffffffu, rs, s);
        if (tx == 0) atomicAdd(&rowAcc[bh * 128 + y0 + i], rs);
    }
    cpart[ty][tx] = colLoc;
    __syncthreads();
#pragma unroll
    for (int i = ty; i < 32; i += 8)
        obt[(x0 + i) * 128 + y0 + tx] = __float2bfloat16_rn(t[tx][i]);
    if (ty == 0) {
        float s = cpart[0][tx] + cpart[1][tx] + cpart[2][tx] + cpart[3][tx]
                + cpart[4][tx] + cpart[5][tx] + cpart[6][tx] + cpart[7][tx];
        atomicAdd(&colAcc[bh * 128 + x0 + tx], s);
    }
}

__global__ void norm_init_kernel(float* a, float* b, float* c, float* d) {
    int i = blockIdx.x * 256 + threadIdx.x;
    if (i < B_ * HEADS_ * 128) { a[i] = 0.f; b[i] = 0.f; c[i] = 0.f; d[i] = 0.f; }
}

// ---------------- conv1x1 (channel-first fp32 in -> fp32 channel-first out, tf32-rounded) ----
#define SAS 36
#define ATS 136
#define CONV_ATBUF (32 * ATS)
#define CONV_WBUF (192 * SAS)
#define SMEM_BYTES ((2 * CONV_ATBUF + 2 * CONV_WBUF) * 4)

__global__ __launch_bounds__(512, 1) void conv_front_kernel(
    const float* __restrict__ x1, const float* __restrict__ x2,
    const float* __restrict__ Wt, const float* __restrict__ bias,
    float* __restrict__ o1, float* __restrict__ o2)
{
    extern __shared__ float sm[];
    const int tid = threadIdx.x;
    const int lane = tid & 31;
    const int g = lane >> 2;
    const int tig = lane & 3;
    const int wid = tid >> 5;
    const int mbase = (wid & 3) * 32;
    const int nbase = (wid >> 2) * 48;
    const int t = blockIdx.x;
    const int pg0 = t << 7;
    const int b = pg0 >> 14;
    const int p0 = pg0 & (HW_ - 1);
    const float* inb = (blockIdx.y ? x2 : x1) + (size_t)b * C_ * HW_;
    float* out = (blockIdx.y ? o2 : o1);

    float c[2][6][4];
#pragma unroll
    for (int mt = 0; mt < 2; mt++)
#pragma unroll
        for (int nt = 0; nt < 6; nt++)
#pragma unroll
            for (int r = 0; r < 4; r++) c[mt][nt][r] = 0.f;

    float4 pa[2], pw[3];
#pragma unroll
    for (int r = 0; r < 2; r++) {
        int f = tid + 512 * r;
        pa[r] = *(const float4*)(inb + (size_t)(f >> 5) * HW_ + p0 + (f & 31) * 4);
    }
#pragma unroll
    for (int r = 0; r < 3; r++) {
        int f = tid + 512 * r;
        pw[r] = *(const float4*)(Wt + (size_t)(f >> 3) * C_ + (f & 7) * 4);
    }

    for (int kc = 0; kc < 6; kc++) {
        float* dA = sm + (kc & 1) * CONV_ATBUF;
        float* dW = sm + 2 * CONV_ATBUF + (kc & 1) * CONV_WBUF;
#pragma unroll
        for (int r = 0; r < 2; r++) {
            int f = tid + 512 * r;
            *(float4*)&dA[(f >> 5) * ATS + (f & 31) * 4] = to_tf32_4(pa[r]);
        }
#pragma unroll
        for (int r = 0; r < 3; r++) {
            int f = tid + 512 * r;
            *(float4*)&dW[(f >> 3) * SAS + (f & 7) * 4] = to_tf32_4(pw[r]);
        }
        __syncthreads();
        if (kc < 5) {
            int ko = (kc + 1) * 32;
#pragma unroll
            for (int r = 0; r < 2; r++) {
                int f = tid + 512 * r;
                pa[r] = *(const float4*)(inb + (size_t)(ko + (f >> 5)) * HW_ + p0 + (f & 31) * 4);
            }
#pragma unroll
            for (int r = 0; r < 3; r++) {
                int f = tid + 512 * r;
                pw[r] = *(const float4*)(Wt + (size_t)(f >> 3) * C_ + ko + (f & 7) * 4);
            }
        }
#pragma unroll
        for (int kk = 0; kk < 4; kk++) {
            const int k0 = kk * 8 + tig;
            uint32_t a[2][4], bb[6][2];
#pragma unroll
            for (int mt = 0; mt < 2; mt++) {
                int row = mbase + mt * 16 + g;
                a[mt][0] = __float_as_uint(dA[k0 * ATS + row]);
                a[mt][1] = __float_as_uint(dA[k0 * ATS + row + 8]);
                a[mt][2] = __float_as_uint(dA[(k0 + 4) * ATS + row]);
                a[mt][3] = __float_as_uint(dA[(k0 + 4) * ATS + row + 8]);
            }
#pragma unroll
            for (int nt = 0; nt < 6; nt++) {
                int col = nbase + nt * 8 + g;
                bb[nt][0] = __float_as_uint(dW[col * SAS + k0]);
                bb[nt][1] = __float_as_uint(dW[col * SAS + k0 + 4]);
            }
#pragma unroll
            for (int mt = 0; mt < 2; mt++)
#pragma unroll
                for (int nt = 0; nt < 6; nt++)
                    mma_tf32(c[mt][nt], a[mt], bb[nt]);
        }
    }

#pragma unroll
    for (int nt = 0; nt < 6; nt++) {
        int o = nbase + nt * 8 + 2 * tig;
        float bv0 = __ldg(&bias[o]);
        float bv1 = __ldg(&bias[o + 1]);
#pragma unroll
        for (int mt = 0; mt < 2; mt++)
#pragma unroll
            for (int half = 0; half < 2; half++) {
                int row = mbase + mt * 16 + g + half * 8;
#pragma unroll
                for (int cc = 0; cc < 2; cc++) {
                    float v = c[mt][nt][half * 2 + cc] + (cc ? bv1 : bv0);
                    out[((size_t)(b * C_ + o + cc) << 14) + p0 + row] = to_tf32(v);
                }
            }
    }
}

// ---------------- fused triple conv (fp32 fus in, fp32 out) ----------------
#define C3_SO_STRIDE 196
#define C3_SO_FLOATS (128 * C3_SO_STRIDE)
#define C3_W_OFF C3_SO_FLOATS
#define C3_SMEM_BYTES ((C3_SO_FLOATS + 2 * CONV_WBUF) * 4)

#define C3_MMALOOP_SO(kbase, dWpt, ACC) do {                                     \
    _Pragma("unroll")                                                            \
    for (int kk = 0; kk < 4; kk++) {                                             \
        const int k0 = kk * 8 + tig;                                             \
        uint32_t a[2][4], bb[6][2];                                              \
        _Pragma("unroll")                                                        \
        for (int mt = 0; mt < 2; mt++) {                                         \
            int row = mbase + mt * 16 + g;                                       \
            a[mt][0] = __float_as_uint(sO[row * C3_SO_STRIDE + (kbase) + k0]);   \
            a[mt][1] = __float_as_uint(sO[(row + 8) * C3_SO_STRIDE + (kbase) + k0]); \
            a[mt][2] = __float_as_uint(sO[row * C3_SO_STRIDE + (kbase) + k0 + 4]); \
            a[mt][3] = __float_as_uint(sO[(row + 8) * C3_SO_STRIDE + (kbase) + k0 + 4]); \
        }                                                                        \
        _Pragma("unroll")                                                        \
        for (int nt = 0; nt < 6; nt++) {                                         \
            int col = nbase + nt * 8 + g;                                        \
            bb[nt][0] = __float_as_uint((dWpt)[col * SAS + k0]);                 \
            bb[nt][1] = __float_as_uint((dWpt)[col * SAS + k0 + 4]);             \
        }                                                                        \
        _Pragma("unroll")                                                        \
        for (int mt = 0; mt < 2; mt++)                                           \
            _Pragma("unroll")                                                    \
            for (int nt = 0; nt < 6; nt++)                                       \
                mma_tf32(ACC[mt][nt], a[mt], bb[nt]);                            \
    }                                                                            \
} while (0)

#define C3_LOADW(Wsrc, ko) do {                                                  \
    _Pragma("unroll")                                                            \
    for (int r = 0; r < 3; r++) {                                                \
        int f = tid + 512 * r;                                                   \
        pw[r] = *(const float4*)((Wsrc) + (size_t)(f >> 3) * C_ + (ko) + (f & 7) * 4); \
    }                                                                            \
} while (0)

#define C3_STOREW(dWpt) do {                                                     \
    _Pragma("unroll")                                                            \
    for (int r = 0; r < 3; r++) {                                                \
        int f = tid + 512 * r;                                                   \
        *(float4*)&(dWpt)[(f >> 3) * SAS + (f & 7) * 4] = to_tf32_4(pw[r]);      \
    }                                                                            \
} while (0)

#define C3_ZEROACC(ACC) do {                                                     \
    _Pragma("unroll")                                                            \
    for (int mt = 0; mt < 2; mt++)                                               \
        _Pragma("unroll")                                                        \
        for (int nt = 0; nt < 6; nt++)                                           \
            _Pragma("unroll")                                                    \
            for (int r = 0; r < 4; r++) ACC[mt][nt][r] = 0.f;                    \
} while (0)

#define C3_EPI_SMEM(ACC, biasp, do_gelu) do {                                    \
    _Pragma("unroll")                                                            \
    for (int nt = 0; nt < 6; nt++) {                                             \
        int o = nbase + nt * 8 + 2 * tig;                                        \
        float bv0 = __ldg(&(biasp)[o]);                                          \
        float bv1 = __ldg(&(biasp)[o + 1]);                                      \
        _Pragma("unroll")                                                        \
        for (int mt = 0; mt < 2; mt++)                                           \
            _Pragma("unroll")                                                    \
            for (int half = 0; half < 2; half++) {                               \
                int row = mbase + mt * 16 + g + half * 8;                        \
                float v0 = ACC[mt][nt][half * 2 + 0] + bv0;                      \
                float v1 = ACC[mt][nt][half * 2 + 1] + bv1;                      \
                if (do_gelu) {                                                   \
                    v0 = 0.5f * v0 * (1.0f + erff(v0 * 0.70710678118654752f));   \
                    v1 = 0.5f * v1 * (1.0f + erff(v1 * 0.70710678118654752f));   \
                }                                                                \
                float2 w = {to_tf32(v0), to_tf32(v1)};                           \
                *(float2*)&sO[row * C3_SO_STRIDE + o] = w;                       \
            }                                                                    \
    }                                                                            \
} while (0)

__global__ __launch_bounds__(512, 1) void conv3x_kernel(
    const float* __restrict__ fus,
    const float* __restrict__ Wp,  const float* __restrict__ bp,
    const float* __restrict__ Wm1, const float* __restrict__ bm1,
    const float* __restrict__ Wm2, const float* __restrict__ bm2,
    const float* __restrict__ r1,  const float* __restrict__ r2,
    float* __restrict__ out)
{
    extern __shared__ float sm[];
    float* sO = sm;
    float* sW = sm + C3_W_OFF;
    const int tid = threadIdx.x;
    const int lane = tid & 31;
    const int g = lane >> 2;
    const int tig = lane & 3;
    const int wid = tid >> 5;
    const int mbase = (wid & 3) * 32;
    const int nbase = (wid >> 2) * 48;
    const int t = blockIdx.x;
    const int pg0 = t << 7;
    const int b = pg0 >> 14;
    const int p0 = pg0 & (HW_ - 1);
    const float* inb = fus + (size_t)b * C_ * HW_;

    float acc[2][6][4];
    float4 pa[2], pw[3];

    C3_ZEROACC(acc);
#pragma unroll
    for (int r = 0; r < 2; r++) {
        int f = tid + 512 * r;
        pa[r] = *(const float4*)(inb + (size_t)(f >> 5) * HW_ + p0 + (f & 31) * 4);
    }
    C3_LOADW(Wp, 0);
    for (int kc = 0; kc < 6; kc++) {
        float* dA = sm + (kc & 1) * CONV_ATBUF;
        float* dW = sW + (kc & 1) * CONV_WBUF;
#pragma unroll
        for (int r = 0; r < 2; r++) {
            int f = tid + 512 * r;
            *(float4*)&dA[(f >> 5) * ATS + (f & 31) * 4] = to_tf32_4(pa[r]);
        }
        C3_STOREW(dW);
        __syncthreads();
        if (kc < 5) {
            int ko = (kc + 1) * 32;
#pragma unroll
            for (int r = 0; r < 2; r++) {
                int f = tid + 512 * r;
                pa[r] = *(const float4*)(inb + (size_t)(ko + (f >> 5)) * HW_ + p0 + (f & 31) * 4);
            }
            C3_LOADW(Wp, ko);
        }
#pragma unroll
        for (int kk = 0; kk < 4; kk++) {
            const int k0 = kk * 8 + tig;
            uint32_t a[2][4], bb[6][2];
#pragma unroll
            for (int mt = 0; mt < 2; mt++) {
                int row = mbase + mt * 16 + g;
                a[mt][0] = __float_as_uint(dA[k0 * ATS + row]);
                a[mt][1] = __float_as_uint(dA[k0 * ATS + row + 8]);
                a[mt][2] = __float_as_uint(dA[(k0 + 4) * ATS + row]);
                a[mt][3] = __float_as_uint(dA[(k0 + 4) * ATS + row + 8]);
            }
#pragma unroll
            for (int nt = 0; nt < 6; nt++) {
                int col = nbase + nt * 8 + g;
                bb[nt][0] = __float_as_uint(dW[col * SAS + k0]);
                bb[nt][1] = __float_as_uint(dW[col * SAS + k0 + 4]);
            }
#pragma unroll
            for (int mt = 0; mt < 2; mt++)
#pragma unroll
                for (int nt = 0; nt < 6; nt++)
                    mma_tf32(acc[mt][nt], a[mt], bb[nt]);
        }
    }
    __syncthreads();
    C3_EPI_SMEM(acc, bp, 0);
    __syncthreads();

    C3_ZEROACC(acc);
    C3_LOADW(Wm1, 0);
    for (int kc = 0; kc < 6; kc++) {
        float* dW = sW + (kc & 1) * CONV_WBUF;
        C3_STOREW(dW);
        __syncthreads();
        if (kc < 5) C3_LOADW(Wm1, (kc + 1) * 32);
        C3_MMALOOP_SO(kc * 32, dW, acc);
    }
    __syncthreads();
    C3_EPI_SMEM(acc, bm1, 1);
    __syncthreads();

    C3_ZEROACC(acc);
    C3_LOADW(Wm2, 0);
    for (int kc = 0; kc < 6; kc++) {
        float* dW = sW + (kc & 1) * CONV_WBUF;
        C3_STOREW(dW);
        __syncthreads();
        if (kc < 5) C3_LOADW(Wm2, (kc + 1) * 32);
        C3_MMALOOP_SO(kc * 32, dW, acc);
    }

#pragma unroll
    for (int nt = 0; nt < 6; nt++) {
        int o = nbase + nt * 8 + 2 * tig;
        float bv0 = __ldg(&bm2[o]);
        float bv1 = __ldg(&bm2[o + 1]);
#pragma unroll
        for (int mt = 0; mt < 2; mt++)
#pragma unroll
            for (int half = 0; half < 2; half++) {
                int row = mbase + mt * 16 + g + half * 8;
#pragma unroll
                for (int cc = 0; cc < 2; cc++) {
                    float v = acc[mt][nt][half * 2 + cc] + (cc ? bv1 : bv0);
                    size_t idx = ((size_t)(b * C_ + o + cc) << 14) + p0 + row;
                    v += __ldg(&r1[idx]) + __ldg(&r2[idx]);
                    out[idx] = v;
                }
            }
    }
}

// ---------------- bf16 pipeline constants (attn/av, 256 thr, M-split 64) ----------------
#define BPAS 36
#define BAB_A (64 * BPAS)
#define BAB_B (128 * BPAS)
#define BPBUF (BAB_A + BAB_B)
#define BPIPE_SMEM_BYTES (2 * BPBUF * 4)

#define BPIPE_STAGE(sbuf32, Ap, Bp) do {                                         \
    _Pragma("unroll")                                                            \
    for (int r = 0; r < 2; r++) {                                                \
        int f = tid + 256 * r;                                                   \
        int row = f >> 3, c8 = f & 7;                                            \
        cpa16((sbuf32) + (row * BPAS + c8 * 4) * 4, (Ap) + row * 128 + c8 * 8);  \
    }                                                                            \
    _Pragma("unroll")                                                            \
    for (int r = 0; r < 4; r++) {                                                \
        int f = tid + 256 * r;                                                   \
        int row = f >> 3, c8 = f & 7;                                            \
        cpa16((sbuf32) + (BAB_A + row * BPAS + c8 * 4) * 4, (Bp) + row * 128 + c8 * 8); \
    }                                                                            \
    CP_COMMIT();                                                                 \
} while (0)

#define BPIPE_MMA(dA, dB, ACC) do {                                              \
    _Pragma("unroll")                                                            \
    for (int w = 0; w < 4; w++) {                                                \
        const int kp = w * 8 + tig;                                              \
        uint32_t a[2][4], bf[4][2];                                              \
        _Pragma("unroll")                                                        \
        for (int mt = 0; mt < 2; mt++) {                                         \
            int row = mbase + mt * 16 + g;                                       \
            a[mt][0] = (dA)[row * BPAS + kp];                                    \
            a[mt][1] = (dA)[(row + 8) * BPAS + kp];                              \
            a[mt][2] = (dA)[row * BPAS + kp + 4];                                \
            a[mt][3] = (dA)[(row + 8) * BPAS + kp + 4];                          \
        }                                                                        \
        _Pragma("unroll")                                                        \
        for (int nt = 0; nt < 4; nt++) {                                         \
            int col = nbase + nt * 8 + g;                                        \
            bf[nt][0] = (dB)[col * BPAS + kp];                                   \
            bf[nt][1] = (dB)[col * BPAS + kp + 4];                               \
        }                                                                        \
        _Pragma("unroll")                                                        \
        for (int mt = 0; mt < 2; mt++)                                           \
            _Pragma("unroll")                                                    \
            for (int nt = 0; nt < 4; nt++)                                       \
                mma_bf16(ACC[mt][nt], a[mt], bf[nt]);                            \
    }                                                                            \
} while (0)

// ---------------- attention: bf16 operands, fused softmax, bf16 output ----------------
__global__ __launch_bounds__(256, 2) void attn_mma_kernel(
    const __nv_bfloat16* __restrict__ o1b, const __nv_bfloat16* __restrict__ o2b,
    const __nv_bfloat16* __restrict__ o1tb, const __nv_bfloat16* __restrict__ o2tb,
    const float* __restrict__ n1h, const float* __restrict__ n2h,
    const float* __restrict__ n1w, const float* __restrict__ n2w,
    const float* __restrict__ pbh, const float* __restrict__ pbw,
    __nv_bfloat16* __restrict__ a1b, __nv_bfloat16* __restrict__ a2b)
{
    extern __shared__ float smf[];
    uint32_t* smu = (uint32_t*)smf;
    const uint32_t sbase = (uint32_t)__cvta_generic_to_shared(smf);
    const int bh = blockIdx.x;
    const int mode = blockIdx.y;
    const int mh = blockIdx.z;
    const int hd = bh & 7, b = bh >> 3;
    const int tid = threadIdx.x;
    const int lane = tid & 31, g = lane >> 2, tig = lane & 3;
    const int wid = tid >> 5;
    const int mbase = (wid & 1) * 32;
    const int nbase = (wid >> 1) * 32;
    const int mh64 = mh * 64;
    const __nv_bfloat16* Abase =
        ((mode ? o1tb : o2b) + ((size_t)b * C_ + hd * CPH_) * HW_) + mh64 * 128;
    const __nv_bfloat16* Bbase = (mode ? o2tb : o1b) + ((size_t)b * C_ + hd * CPH_) * HW_;

    float acc[2][4][4];
#pragma unroll
    for (int mt = 0; mt < 2; mt++)
#pragma unroll
        for (int nt = 0; nt < 4; nt++)
#pragma unroll
            for (int e = 0; e < 4; e++) acc[mt][nt][e] = 0.f;

    BPIPE_STAGE(sbase, Abase, Bbase);
    for (int kc = 0; kc < 48; kc++) {
        if (kc < 47) {
            int kn = kc + 1;
            const __nv_bfloat16* Ap = Abase + (kn >> 1) * HW_ + (kn & 1) * 64;
            const __nv_bfloat16* Bp = Bbase + (kn >> 1) * HW_ + (kn & 1) * 64;
            uint32_t sbuf = sbase + ((kn & 1) * BPBUF) * 4;
            BPIPE_STAGE(sbuf, Ap, Bp);
            CP_WAIT1();
        } else {
            CP_WAIT0();
        }
        __syncthreads();
        const uint32_t* dA = smu + (kc & 1) * BPBUF;
        const uint32_t* dB = dA + BAB_A;
        BPIPE_MMA(dA, dB, acc);
        __syncthreads();
    }

    const float* nI = mode ? n1w : n2h;
    const float* nJ = mode ? n2w : n1h;
    const float bias = mode ? __ldg(&pbw[hd]) : __ldg(&pbh[hd]);
    float rinv[4], cinv[8];
#pragma unroll
    for (int mt = 0; mt < 2; mt++)
#pragma unroll
        for (int half = 0; half < 2; half++) {
            int row = mbase + mt * 16 + g + half * 8;
            rinv[mt * 2 + half] =
                TEMP_INV / fmaxf(sqrtf(__ldg(&nI[bh * 128 + mh64 + row])), EPS_);
        }
#pragma unroll
    for (int nt = 0; nt < 4; nt++)
#pragma unroll
        for (int cc = 0; cc < 2; cc++) {
            int col = nbase + nt * 8 + 2 * tig + cc;
            cinv[nt * 2 + cc] = 1.f / fmaxf(sqrtf(__ldg(&nJ[bh * 128 + col])), EPS_);
        }
    float* sc = smf;
#pragma unroll
    for (int mt = 0; mt < 2; mt++)
#pragma unroll
        for (int half = 0; half < 2; half++) {
            int row = mbase + mt * 16 + g + half * 8;
            float ri = rinv[mt * 2 + half];
#pragma unroll
            for (int nt = 0; nt < 4; nt++) {
                int col = nbase + nt * 8 + 2 * tig;
                float2 v;
                v.x = acc[mt][nt][half * 2 + 0] * (ri * cinv[nt * 2 + 0]) + bias;
                v.y = acc[mt][nt][half * 2 + 1] * (ri * cinv[nt * 2 + 1]) + bias;
                *(float2*)&sc[row * 132 + col] = v;
            }
        }
    __syncthreads();

    __nv_bfloat16* outp = (mode ? a2b : a1b) + (size_t)bh * HW_ + mh64 * 128;
    for (int r = wid; r < 64; r += 8) {
        float4 v = *(float4*)&sc[r * 132 + lane * 4];
        float m = fmaxf(fmaxf(v.x, v.y), fmaxf(v.z, v.w));
#pragma unroll
        for (int s = 16; s >= 1; s >>= 1) m = fmaxf(m, __shfl_xor_sync(0xffffffffu, m, s));
        v.x = __expf(v.x - m); v.y = __expf(v.y - m);
        v.z = __expf(v.z - m); v.w = __expf(v.w - m);
        float su = v.x + v.y + v.z + v.w;
#pragma unroll
        for (int s = 16; s >= 1; s >>= 1) su += __shfl_xor_sync(0xffffffffu, su, s);
        float inv = 1.f / su;
        uint2 o;
        o.x = f2bf2(v.x * inv, v.y * inv);
        o.y = f2bf2(v.z * inv, v.w * inv);
        *(uint2*)&outp[r * 128 + lane * 4] = o;
    }
}

// ---------------- AV + q-residual + gated fusion: bf16 GEMMs, bf16 S reads ----------------
__global__ __launch_bounds__(256, 2) void av_mma_kernel(
    const __nv_bfloat16* __restrict__ o1b, const __nv_bfloat16* __restrict__ o2b,
    const __nv_bfloat16* __restrict__ o1tb,
    const __nv_bfloat16* __restrict__ a1b, const __nv_bfloat16* __restrict__ a2b,
    const float* __restrict__ n2h, const float* __restrict__ n1w,
    const float* __restrict__ gate, float* __restrict__ fus)
{
    extern __shared__ float smf[];
    uint32_t* smu = (uint32_t*)smf;
    const uint32_t sbase = (uint32_t)__cvta_generic_to_shared(smf);
    const int ch = blockIdx.x, b = blockIdx.y;
    const int mh = blockIdx.z;
    const int hd = ch / CPH_;
    const int bh = b * 8 + hd;
    const int tid = threadIdx.x;
    const int lane = tid & 31, g = lane >> 2, tig = lane & 3;
    const int wid = tid >> 5;
    const int mbase = (wid & 1) * 32;
    const int nbase = (wid >> 1) * 32;
    const int mh64 = mh * 64;

    const __nv_bfloat16* A1 = a1b + (size_t)bh * HW_ + mh64 * 128;
    const __nv_bfloat16* B1 = o1tb + ((size_t)b * C_ + ch) * HW_;
    const __nv_bfloat16* A2 = o2b + ((size_t)b * C_ + ch) * HW_ + mh64 * 128;
    const __nv_bfloat16* B2 = a2b + (size_t)bh * HW_;
    const __nv_bfloat16* S1 = o1b + ((size_t)b * C_ + ch) * HW_;
    const __nv_bfloat16* S2 = o2b + ((size_t)b * C_ + ch) * HW_;

    float acc1[2][4][4], acc2[2][4][4];
#pragma unroll
    for (int mt = 0; mt < 2; mt++)
#pragma unroll
        for (int nt = 0; nt < 4; nt++)
#pragma unroll
            for (int e = 0; e < 4; e++) { acc1[mt][nt][e] = 0.f; acc2[mt][nt][e] = 0.f; }

    const uint32_t sb0 = sbase;
    const uint32_t sb1 = sbase + BPBUF * 4;
    const uint32_t* dA0 = smu;
    const uint32_t* dB0 = smu + BAB_A;
    const uint32_t* dA1 = smu + BPBUF;
    const uint32_t* dB1 = smu + BPBUF + BAB_A;

    BPIPE_STAGE(sb0, A1, B1);
    BPIPE_STAGE(sb1, A1 + 64, B1 + 64);
    CP_WAIT1(); __syncthreads();
    BPIPE_MMA(dA0, dB0, acc1);
    __syncthreads();
    BPIPE_STAGE(sb0, A2, B2);
    CP_WAIT1(); __syncthreads();
    BPIPE_MMA(dA1, dB1, acc1);
    __syncthreads();
    BPIPE_STAGE(sb1, A2 + 64, B2 + 64);
    CP_WAIT1(); __syncthreads();
    BPIPE_MMA(dA0, dB0, acc2);
    CP_WAIT0(); __syncthreads();
    BPIPE_MMA(dA1, dB1, acc2);

    const float gg = 1.f / (1.f + expf(-__ldg(&gate[0])));
    float invy[4], invx[8];
#pragma unroll
    for (int mt = 0; mt < 2; mt++)
#pragma unroll
        for (int half = 0; half < 2; half++) {
            int row = mbase + mt * 16 + g + half * 8;
            invy[mt * 2 + half] =
                1.f / fmaxf(sqrtf(__ldg(&n2h[bh * 128 + mh64 + row])), EPS_);
        }
#pragma unroll
    for (int nt = 0; nt < 4; nt++)
#pragma unroll
        for (int cc = 0; cc < 2; cc++) {
            int col = nbase + nt * 8 + 2 * tig + cc;
            invx[nt * 2 + cc] = 1.f / fmaxf(sqrtf(__ldg(&n1w[bh * 128 + col])), EPS_);
        }

    float* fout = fus + ((size_t)b * C_ + ch) * HW_;
#pragma unroll
    for (int mt = 0; mt < 2; mt++)
#pragma unroll
        for (int half = 0; half < 2; half++) {
            int rl = mbase + mt * 16 + g + half * 8;
            int row = mh64 + rl;
            float iy = invy[mt * 2 + half];
#pragma unroll
            for (int nt = 0; nt < 4; nt++) {
                int col = nbase + nt * 8 + 2 * tig;
                float2 s1f = __bfloat1622float2(*(const __nv_bfloat162*)(S1 + row * 128 + col));
                float2 s2f = __bfloat1622float2(*(const __nv_bfloat162*)(S2 + row * 128 + col));
                float2 o;
                o.x = gg * (acc1[mt][nt][half * 2 + 0] + s2f.x * iy)
                    + (1.f - gg) * (acc2[mt][nt][half * 2 + 0] + s1f.x * invx[nt * 2 + 0]);
                o.y = gg * (acc1[mt][nt][half * 2 + 1] + s2f.y * iy)
                    + (1.f - gg) * (acc2[mt][nt][half * 2 + 1] + s1f.y * invx[nt * 2 + 1]);
                *(float2*)(fout + row * 128 + col) = o;
            }
        }
}

// ---------------- host launcher ----------------
extern "C" void kernel_launch(void* const* d_in, const int* in_sizes, int n_in,
                              void* d_out, int out_size)
{
    const float* x1  = (const float*)d_in[0];
    const float* x2  = (const float*)d_in[1];
    const float* Wp  = (const float*)d_in[2];
    const float* bp  = (const float*)d_in[3];
    const float* gate= (const float*)d_in[4];
    const float* pbh = (const float*)d_in[5];
    const float* pbw = (const float*)d_in[6];
    const float* Wm1 = (const float*)d_in[7];
    const float* bm1 = (const float*)d_in[8];
    const float* Wm2 = (const float*)d_in[9];
    const float* bm2 = (const float*)d_in[10];
    float* out = (float*)d_out;

    float *p_o1, *p_o2, *p_fus, *p_n1h, *p_n2h, *p_n1w, *p_n2w;
    __nv_bfloat16 *p_o1b, *p_o2b, *p_o1tb, *p_o2tb, *p_a1b, *p_a2b;
    cudaGetSymbolAddress((void**)&p_o1, g_o1);
    cudaGetSymbolAddress((void**)&p_o2, g_o2);
    cudaGetSymbolAddress((void**)&p_fus, g_fus);
    cudaGetSymbolAddress((void**)&p_o1b, g_o1b);
    cudaGetSymbolAddress((void**)&p_o2b, g_o2b);
    cudaGetSymbolAddress((void**)&p_o1tb, g_o1tb);
    cudaGetSymbolAddress((void**)&p_o2tb, g_o2tb);
    cudaGetSymbolAddress((void**)&p_a1b, g_a1b);
    cudaGetSymbolAddress((void**)&p_a2b, g_a2b);
    cudaGetSymbolAddress((void**)&p_n1h, g_n1h);
    cudaGetSymbolAddress((void**)&p_n2h, g_n2h);
    cudaGetSymbolAddress((void**)&p_n1w, g_n1w);
    cudaGetSymbolAddress((void**)&p_n2w, g_n2w);

    cudaFuncSetAttribute(conv_front_kernel, cudaFuncAttributeMaxDynamicSharedMemorySize, SMEM_BYTES);
    cudaFuncSetAttribute(conv3x_kernel, cudaFuncAttributeMaxDynamicSharedMemorySize, C3_SMEM_BYTES);
    cudaFuncSetAttribute(attn_mma_kernel, cudaFuncAttributeMaxDynamicSharedMemorySize, BPIPE_SMEM_BYTES);
    cudaFuncSetAttribute(av_mma_kernel, cudaFuncAttributeMaxDynamicSharedMemorySize, BPIPE_SMEM_BYTES);

    conv_front_kernel<<<dim3(NTILES_, 2), 512, SMEM_BYTES>>>(x1, x2, Wp, bp, p_o1, p_o2);

    norm_init_kernel<<<32, 256>>>(p_n1h, p_n1w, p_n2h, p_n2w);
    repack_norm_kernel<<<dim3(16, 2 * C_, B_), dim3(32, 8)>>>(
        p_o1, p_o2, p_o1b, p_o2b, p_o1tb, p_o2tb, p_n1h, p_n1w, p_n2h, p_n2w);

    attn_mma_kernel<<<dim3(B_ * HEADS_, 2, 2), 256, BPIPE_SMEM_BYTES>>>(
        p_o1b, p_o2b, p_o1tb, p_o2tb, p_n1h, p_n2h, p_n1w, p_n2w, pbh, pbw, p_a1b, p_a2b);

    av_mma_kernel<<<dim3(C_, B_, 2), 256, BPIPE_SMEM_BYTES>>>(
        p_o1b, p_o2b, p_o1tb, p_a1b, p_a2b, p_n2h, p_n1w, gate, p_fus);

    conv3x_kernel<<<NTILES_, 512, C3_SMEM_BYTES>>>(p_fus, Wp, bp, Wm1, bm1, Wm2, bm2,
                                                   x1, x2, out);

    (void)in_sizes; (void)n_in; (void)out_size;
}

// round 15
// speedup vs baseline: 1.6920x; 1.2084x over previous
#include <cuda_runtime.h>
#include <cuda_bf16.h>
#include <math.h>
#include <stdint.h>

#define B_ 8
#define C_ 192
#define H_ 128
#define W_ 128
#define HW_ 16384
#define HEADS_ 8
#define CPH_ 24
#define TEMP_INV 100.0f
#define EPS_ 1e-12f

#define NPIX_ (B_ * HW_)
#define NTILES_ (NPIX_ / 128)

// ---------------- scratch ----------------
__device__ float g_fus[(size_t)B_ * C_ * HW_];
__device__ __nv_bfloat16 g_o1b[(size_t)B_ * C_ * HW_];   // [y][x] bf16
__device__ __nv_bfloat16 g_o2b[(size_t)B_ * C_ * HW_];
__device__ __nv_bfloat16 g_o1tb[(size_t)B_ * C_ * HW_];  // [x][y] bf16
__device__ __nv_bfloat16 g_o2tb[(size_t)B_ * C_ * HW_];
__device__ __nv_bfloat16 g_a1b[(size_t)B_ * HEADS_ * HW_];
__device__ __nv_bfloat16 g_a2b[(size_t)B_ * HEADS_ * HW_];
__device__ float g_n1h[B_ * HEADS_ * H_];   // squared sums (sqrt at consumer)
__device__ float g_n2h[B_ * HEADS_ * H_];
__device__ float g_n1w[B_ * HEADS_ * W_];
__device__ float g_n2w[B_ * HEADS_ * W_];

__device__ __forceinline__ float to_tf32(float x) {
    uint32_t u; asm("cvt.rna.tf32.f32 %0, %1;" : "=r"(u) : "f"(x));
    return __uint_as_float(u);
}
__device__ __forceinline__ float4 to_tf32_4(float4 v) {
    v.x = to_tf32(v.x); v.y = to_tf32(v.y); v.z = to_tf32(v.z); v.w = to_tf32(v.w);
    return v;
}
__device__ __forceinline__ uint32_t f2bf2(float a, float b) {
    __nv_bfloat162 h = __floats2bfloat162_rn(a, b);
    return *(uint32_t*)&h;
}

__device__ __forceinline__ void mma_tf32(float* c, const uint32_t* a, const uint32_t* b) {
    asm volatile(
        "mma.sync.aligned.m16n8k8.row.col.f32.tf32.tf32.f32 "
        "{%0,%1,%2,%3}, {%4,%5,%6,%7}, {%8,%9}, {%0,%1,%2,%3};"
        : "+f"(c[0]), "+f"(c[1]), "+f"(c[2]), "+f"(c[3])
        : "r"(a[0]), "r"(a[1]), "r"(a[2]), "r"(a[3]), "r"(b[0]), "r"(b[1]));
}
__device__ __forceinline__ void mma_bf16(float* c, const uint32_t* a, const uint32_t* b) {
    asm volatile(
        "mma.sync.aligned.m16n8k16.row.col.f32.bf16.bf16.f32 "
        "{%0,%1,%2,%3}, {%4,%5,%6,%7}, {%8,%9}, {%0,%1,%2,%3};"
        : "+f"(c[0]), "+f"(c[1]), "+f"(c[2]), "+f"(c[3])
        : "r"(a[0]), "r"(a[1]), "r"(a[2]), "r"(a[3]), "r"(b[0]), "r"(b[1]));
}

__device__ __forceinline__ void cpa16(uint32_t s, const void* g) {
    asm volatile("cp.async.cg.shared.global [%0], [%1], 16;" :: "r"(s), "l"(g));
}
#define CP_COMMIT() asm volatile("cp.async.commit_group;" ::: "memory")
#define CP_WAIT1()  asm volatile("cp.async.wait_group 1;" ::: "memory")
#define CP_WAIT0()  asm volatile("cp.async.wait_group 0;" ::: "memory")

__global__ void norm_init_kernel(float* a, float* b, float* c, float* d) {
    int i = blockIdx.x * 256 + threadIdx.x;
    if (i < B_ * HEADS_ * 128) { a[i] = 0.f; b[i] = 0.f; c[i] = 0.f; d[i] = 0.f; }
}

// ---------------- conv1x1 front: fp32 channel-first in -> bf16 channel-first out + norms ----
// Each CTA = one (b, y) row, all 192 channels. Row norms written directly; col norms via atomics.
#define SAS 36
#define ATS 136
#define CONV_ATBUF (32 * ATS)
#define CONV_WBUF (192 * SAS)
#define SMEM_BYTES ((2 * CONV_ATBUF + 2 * CONV_WBUF) * 4)   // 90112
// epilogue aliases: sBF [192][132] bf16 (50688 B) + spart [128][8] f32 (4096 B) = 54784 < 90112
#define SBF_STRIDE 132
#define SPART_FOFF ((192 * SBF_STRIDE) / 2)   // float offset of spart

__global__ __launch_bounds__(512, 1) void conv_front_kernel(
    const float* __restrict__ x1, const float* __restrict__ x2,
    const float* __restrict__ Wt, const float* __restrict__ bias,
    __nv_bfloat16* __restrict__ o1b, __nv_bfloat16* __restrict__ o2b,
    float* __restrict__ n1h, float* __restrict__ n1w,
    float* __restrict__ n2h, float* __restrict__ n2w)
{
    extern __shared__ float sm[];
    const int tid = threadIdx.x;
    const int lane = tid & 31;
    const int g = lane >> 2;
    const int tig = lane & 3;
    const int wid = tid >> 5;
    const int mbase = (wid & 3) * 32;
    const int nbase = (wid >> 2) * 48;
    const int h0 = nbase / 24;               // first head covered by this warp's 48 channels
    const int t = blockIdx.x;
    const int pg0 = t << 7;
    const int b = pg0 >> 14;
    const int p0 = pg0 & (HW_ - 1);
    const float* inb = (blockIdx.y ? x2 : x1) + (size_t)b * C_ * HW_;

    float c[2][6][4];
#pragma unroll
    for (int mt = 0; mt < 2; mt++)
#pragma unroll
        for (int nt = 0; nt < 6; nt++)
#pragma unroll
            for (int r = 0; r < 4; r++) c[mt][nt][r] = 0.f;

    float4 pa[2], pw[3];
#pragma unroll
    for (int r = 0; r < 2; r++) {
        int f = tid + 512 * r;
        pa[r] = *(const float4*)(inb + (size_t)(f >> 5) * HW_ + p0 + (f & 31) * 4);
    }
#pragma unroll
    for (int r = 0; r < 3; r++) {
        int f = tid + 512 * r;
        pw[r] = *(const float4*)(Wt + (size_t)(f >> 3) * C_ + (f & 7) * 4);
    }

    for (int kc = 0; kc < 6; kc++) {
        float* dA = sm + (kc & 1) * CONV_ATBUF;
        float* dW = sm + 2 * CONV_ATBUF + (kc & 1) * CONV_WBUF;
#pragma unroll
        for (int r = 0; r < 2; r++) {
            int f = tid + 512 * r;
            *(float4*)&dA[(f >> 5) * ATS + (f & 31) * 4] = to_tf32_4(pa[r]);
        }
#pragma unroll
        for (int r = 0; r < 3; r++) {
            int f = tid + 512 * r;
            *(float4*)&dW[(f >> 3) * SAS + (f & 7) * 4] = to_tf32_4(pw[r]);
        }
        __syncthreads();
        if (kc < 5) {
            int ko = (kc + 1) * 32;
#pragma unroll
            for (int r = 0; r < 2; r++) {
                int f = tid + 512 * r;
                pa[r] = *(const float4*)(inb + (size_t)(ko + (f >> 5)) * HW_ + p0 + (f & 31) * 4);
            }
#pragma unroll
            for (int r = 0; r < 3; r++) {
                int f = tid + 512 * r;
                pw[r] = *(const float4*)(Wt + (size_t)(f >> 3) * C_ + ko + (f & 7) * 4);
            }
        }
#pragma unroll
        for (int kk = 0; kk < 4; kk++) {
            const int k0 = kk * 8 + tig;
            uint32_t a[2][4], bb[6][2];
#pragma unroll
            for (int mt = 0; mt < 2; mt++) {
                int row = mbase + mt * 16 + g;
                a[mt][0] = __float_as_uint(dA[k0 * ATS + row]);
                a[mt][1] = __float_as_uint(dA[k0 * ATS + row + 8]);
                a[mt][2] = __float_as_uint(dA[(k0 + 4) * ATS + row]);
                a[mt][3] = __float_as_uint(dA[(k0 + 4) * ATS + row + 8]);
            }
#pragma unroll
            for (int nt = 0; nt < 6; nt++) {
                int col = nbase + nt * 8 + g;
                bb[nt][0] = __float_as_uint(dW[col * SAS + k0]);
                bb[nt][1] = __float_as_uint(dW[col * SAS + k0 + 4]);
            }
#pragma unroll
            for (int mt = 0; mt < 2; mt++)
#pragma unroll
                for (int nt = 0; nt < 6; nt++)
                    mma_tf32(c[mt][nt], a[mt], bb[nt]);
        }
    }
    __syncthreads();   // done with dA/dW; reuse smem for epilogue

    __nv_bfloat16* sBF = (__nv_bfloat16*)sm;          // [192][SBF_STRIDE]
    float* spart = sm + SPART_FOFF;                   // [128][8]

    // zero spart
#pragma unroll
    for (int i = tid; i < 128 * 8; i += 512) spart[i] = 0.f;
    __syncthreads();

    float bv[6][2];
#pragma unroll
    for (int nt = 0; nt < 6; nt++) {
        int o = nbase + nt * 8 + 2 * tig;
        bv[nt][0] = __ldg(&bias[o]);
        bv[nt][1] = __ldg(&bias[o + 1]);
    }

#pragma unroll
    for (int mt = 0; mt < 2; mt++)
#pragma unroll
        for (int half = 0; half < 2; half++) {
            int row = mbase + mt * 16 + g + half * 8;
            float s0 = 0.f, s1 = 0.f;
#pragma unroll
            for (int nt = 0; nt < 6; nt++) {
                int o = nbase + nt * 8 + 2 * tig;
                float v0 = c[mt][nt][half * 2 + 0] + bv[nt][0];
                float v1 = c[mt][nt][half * 2 + 1] + bv[nt][1];
                sBF[o * SBF_STRIDE + row] = __float2bfloat16_rn(v0);
                sBF[(o + 1) * SBF_STRIDE + row] = __float2bfloat16_rn(v1);
                float sq = v0 * v0 + v1 * v1;
                if (nt < 3) s0 += sq; else s1 += sq;
            }
            s0 += __shfl_xor_sync(0xffffffffu, s0, 1);
            s0 += __shfl_xor_sync(0xffffffffu, s0, 2);
            s1 += __shfl_xor_sync(0xffffffffu, s1, 1);
            s1 += __shfl_xor_sync(0xffffffffu, s1, 2);
            if (tig == 0) {
                atomicAdd(&spart[row * 8 + h0], s0);
                atomicAdd(&spart[row * 8 + h0 + 1], s1);
            }
        }
    __syncthreads();

    // coalesced bf16 global writes: [c][pix] from sBF
    __nv_bfloat16* outp = (blockIdx.y ? o2b : o1b);
#pragma unroll
    for (int r = 0; r < 24; r++) {
        int f = tid + 512 * r;                    // 12288 uints
        int cch = f >> 6, xu = f & 63;
        uint32_t u = *(uint32_t*)&sBF[cch * SBF_STRIDE + 2 * xu];
        *(uint32_t*)&outp[((size_t)(b * C_ + cch) << 14) + p0 + 2 * xu] = u;
    }

    // norms
    float* rowAcc = blockIdx.y ? n2h : n1h;
    float* colAcc = blockIdx.y ? n2w : n1w;
    const int y = p0 >> 7;
    if (tid < 256) {
        int head = tid >> 5, l = tid & 31;
        float s = spart[l * 8 + head] + spart[(l + 32) * 8 + head]
                + spart[(l + 64) * 8 + head] + spart[(l + 96) * 8 + head];
#pragma unroll
        for (int sh = 16; sh >= 1; sh >>= 1) s += __shfl_xor_sync(0xffffffffu, s, sh);
        if (l == 0) rowAcc[(b * 8 + head) * 128 + y] = s;
    }
#pragma unroll
    for (int r = 0; r < 2; r++) {
        int f = tid + 512 * r;                    // 1024
        int x = f >> 3, head = f & 7;
        atomicAdd(&colAcc[(b * 8 + head) * 128 + x], spart[x * 8 + head]);
    }
}

// ---------------- slim repack: bf16 [y][x] -> bf16 [x][y], 64x64 tiles ----------------
__global__ __launch_bounds__(256) void repackT_kernel(
    const __nv_bfloat16* __restrict__ o1b, const __nv_bfloat16* __restrict__ o2b,
    __nv_bfloat16* __restrict__ o1tb, __nv_bfloat16* __restrict__ o2tb)
{
    __shared__ __nv_bfloat16 t[64][66];
    const int cy = blockIdx.y;
    const int src = cy >= C_;
    const int c = src ? cy - C_ : cy;
    const int b = blockIdx.z;
    const int x0 = (blockIdx.x & 1) * 64, y0 = (blockIdx.x >> 1) * 64;
    const int tid = threadIdx.x;
    const __nv_bfloat16* ib = (src ? o2b : o1b) + ((size_t)b * C_ + c) * HW_;
    __nv_bfloat16* ob = (src ? o2tb : o1tb) + ((size_t)b * C_ + c) * HW_;
#pragma unroll
    for (int r = 0; r < 8; r++) {
        int f = tid + 256 * r;                    // 2048 uints
        int row = f >> 5, xu = f & 31;
        uint32_t u = *(const uint32_t*)&ib[(y0 + row) * 128 + x0 + 2 * xu];
        __nv_bfloat162 h2 = *(__nv_bfloat162*)&u;
        t[2 * xu][row] = h2.x;
        t[2 * xu + 1][row] = h2.y;
    }
    __syncthreads();
#pragma unroll
    for (int r = 0; r < 8; r++) {
        int f = tid + 256 * r;
        int xr = f >> 5, yu = f & 31;
        uint32_t u = *(uint32_t*)&t[xr][2 * yu];
        *(uint32_t*)&ob[(x0 + xr) * 128 + y0 + 2 * yu] = u;
    }
}

// ---------------- fused triple conv (fp32 fus in, fp32 out) ----------------
#define C3_SO_STRIDE 196
#define C3_SO_FLOATS (128 * C3_SO_STRIDE)
#define C3_W_OFF C3_SO_FLOATS
#define C3_SMEM_BYTES ((C3_SO_FLOATS + 2 * CONV_WBUF) * 4)

#define C3_MMALOOP_SO(kbase, dWpt, ACC) do {                                     \
    _Pragma("unroll")                                                            \
    for (int kk = 0; kk < 4; kk++) {                                             \
        const int k0 = kk * 8 + tig;                                             \
        uint32_t a[2][4], bb[6][2];                                              \
        _Pragma("unroll")                                                        \
        for (int mt = 0; mt < 2; mt++) {                                         \
            int row = mbase + mt * 16 + g;                                       \
            a[mt][0] = __float_as_uint(sO[row * C3_SO_STRIDE + (kbase) + k0]);   \
            a[mt][1] = __float_as_uint(sO[(row + 8) * C3_SO_STRIDE + (kbase) + k0]); \
            a[mt][2] = __float_as_uint(sO[row * C3_SO_STRIDE + (kbase) + k0 + 4]); \
            a[mt][3] = __float_as_uint(sO[(row + 8) * C3_SO_STRIDE + (kbase) + k0 + 4]); \
        }                                                                        \
        _Pragma("unroll")                                                        \
        for (int nt = 0; nt < 6; nt++) {                                         \
            int col = nbase + nt * 8 + g;                                        \
            bb[nt][0] = __float_as_uint((dWpt)[col * SAS + k0]);                 \
            bb[nt][1] = __float_as_uint((dWpt)[col * SAS + k0 + 4]);             \
        }                                                                        \
        _Pragma("unroll")                                                        \
        for (int mt = 0; mt < 2; mt++)                                           \
            _Pragma("unroll")                                                    \
            for (int nt = 0; nt < 6; nt++)                                       \
                mma_tf32(ACC[mt][nt], a[mt], bb[nt]);                            \
    }                                                                            \
} while (0)

#define C3_LOADW(Wsrc, ko) do {                                                  \
    _Pragma("unroll")                                                            \
    for (int r = 0; r < 3; r++) {                                                \
        int f = tid + 512 * r;                                                   \
        pw[r] = *(const float4*)((Wsrc) + (size_t)(f >> 3) * C_ + (ko) + (f & 7) * 4); \
    }                                                                            \
} while (0)

#define C3_STOREW(dWpt) do {                                                     \
    _Pragma("unroll")                                                            \
    for (int r = 0; r < 3; r++) {                                                \
        int f = tid + 512 * r;                                                   \
        *(float4*)&(dWpt)[(f >> 3) * SAS + (f & 7) * 4] = to_tf32_4(pw[r]);      \
    }                                                                            \
} while (0)

#define C3_ZEROACC(ACC) do {                                                     \
    _Pragma("unroll")                                                            \
    for (int mt = 0; mt < 2; mt++)                                               \
        _Pragma("unroll")                                                        \
        for (int nt = 0; nt < 6; nt++)                                           \
            _Pragma("unroll")                                                    \
            for (int r = 0; r < 4; r++) ACC[mt][nt][r] = 0.f;                    \
} while (0)

#define C3_EPI_SMEM(ACC, biasp, do_gelu) do {                                    \
    _Pragma("unroll")                                                            \
    for (int nt = 0; nt < 6; nt++) {                                             \
        int o = nbase + nt * 8 + 2 * tig;                                        \
        float bv0 = __ldg(&(biasp)[o]);                                          \
        float bv1 = __ldg(&(biasp)[o + 1]);                                      \
        _Pragma("unroll")                                                        \
        for (int mt = 0; mt < 2; mt++)                                           \
            _Pragma("unroll")                                                    \
            for (int half = 0; half < 2; half++) {                               \
                int row = mbase + mt * 16 + g + half * 8;                        \
                float v0 = ACC[mt][nt][half * 2 + 0] + bv0;                      \
                float v1 = ACC[mt][nt][half * 2 + 1] + bv1;                      \
                if (do_gelu) {                                                   \
                    v0 = 0.5f * v0 * (1.0f + erff(v0 * 0.70710678118654752f));   \
                    v1 = 0.5f * v1 * (1.0f + erff(v1 * 0.70710678118654752f));   \
                }                                                                \
                float2 w = {to_tf32(v0), to_tf32(v1)};                           \
                *(float2*)&sO[row * C3_SO_STRIDE + o] = w;                       \
            }                                                                    \
    }                                                                            \
} while (0)

__global__ __launch_bounds__(512, 1) void conv3x_kernel(
    const float* __restrict__ fus,
    const float* __restrict__ Wp,  const float* __restrict__ bp,
    const float* __restrict__ Wm1, const float* __restrict__ bm1,
    const float* __restrict__ Wm2, const float* __restrict__ bm2,
    const float* __restrict__ r1,  const float* __restrict__ r2,
    float* __restrict__ out)
{
    extern __shared__ float sm[];
    float* sO = sm;
    float* sW = sm + C3_W_OFF;
    const int tid = threadIdx.x;
    const int lane = tid & 31;
    const int g = lane >> 2;
    const int tig = lane & 3;
    const int wid = tid >> 5;
    const int mbase = (wid & 3) * 32;
    const int nbase = (wid >> 2) * 48;
    const int t = blockIdx.x;
    const int pg0 = t << 7;
    const int b = pg0 >> 14;
    const int p0 = pg0 & (HW_ - 1);
    const float* inb = fus + (size_t)b * C_ * HW_;

    float acc[2][6][4];
    float4 pa[2], pw[3];

    C3_ZEROACC(acc);
#pragma unroll
    for (int r = 0; r < 2; r++) {
        int f = tid + 512 * r;
        pa[r] = *(const float4*)(inb + (size_t)(f >> 5) * HW_ + p0 + (f & 31) * 4);
    }
    C3_LOADW(Wp, 0);
    for (int kc = 0; kc < 6; kc++) {
        float* dA = sm + (kc & 1) * CONV_ATBUF;
        float* dW = sW + (kc & 1) * CONV_WBUF;
#pragma unroll
        for (int r = 0; r < 2; r++) {
            int f = tid + 512 * r;
            *(float4*)&dA[(f >> 5) * ATS + (f & 31) * 4] = to_tf32_4(pa[r]);
        }
        C3_STOREW(dW);
        __syncthreads();
        if (kc < 5) {
            int ko = (kc + 1) * 32;
#pragma unroll
            for (int r = 0; r < 2; r++) {
                int f = tid + 512 * r;
                pa[r] = *(const float4*)(inb + (size_t)(ko + (f >> 5)) * HW_ + p0 + (f & 31) * 4);
            }
            C3_LOADW(Wp, ko);
        }
#pragma unroll
        for (int kk = 0; kk < 4; kk++) {
            const int k0 = kk * 8 + tig;
            uint32_t a[2][4], bb[6][2];
#pragma unroll
            for (int mt = 0; mt < 2; mt++) {
                int row = mbase + mt * 16 + g;
                a[mt][0] = __float_as_uint(dA[k0 * ATS + row]);
                a[mt][1] = __float_as_uint(dA[k0 * ATS + row + 8]);
                a[mt][2] = __float_as_uint(dA[(k0 + 4) * ATS + row]);
                a[mt][3] = __float_as_uint(dA[(k0 + 4) * ATS + row + 8]);
            }
#pragma unroll
            for (int nt = 0; nt < 6; nt++) {
                int col = nbase + nt * 8 + g;
                bb[nt][0] = __float_as_uint(dW[col * SAS + k0]);
                bb[nt][1] = __float_as_uint(dW[col * SAS + k0 + 4]);
            }
#pragma unroll
            for (int mt = 0; mt < 2; mt++)
#pragma unroll
                for (int nt = 0; nt < 6; nt++)
                    mma_tf32(acc[mt][nt], a[mt], bb[nt]);
        }
    }
    __syncthreads();
    C3_EPI_SMEM(acc, bp, 0);
    __syncthreads();

    C3_ZEROACC(acc);
    C3_LOADW(Wm1, 0);
    for (int kc = 0; kc < 6; kc++) {
        float* dW = sW + (kc & 1) * CONV_WBUF;
        C3_STOREW(dW);
        __syncthreads();
        if (kc < 5) C3_LOADW(Wm1, (kc + 1) * 32);
        C3_MMALOOP_SO(kc * 32, dW, acc);
    }
    __syncthreads();
    C3_EPI_SMEM(acc, bm1, 1);
    __syncthreads();

    C3_ZEROACC(acc);
    C3_LOADW(Wm2, 0);
    for (int kc = 0; kc < 6; kc++) {
        float* dW = sW + (kc & 1) * CONV_WBUF;
        C3_STOREW(dW);
        __syncthreads();
        if (kc < 5) C3_LOADW(Wm2, (kc + 1) * 32);
        C3_MMALOOP_SO(kc * 32, dW, acc);
    }

#pragma unroll
    for (int nt = 0; nt < 6; nt++) {
        int o = nbase + nt * 8 + 2 * tig;
        float bv0 = __ldg(&bm2[o]);
        float bv1 = __ldg(&bm2[o + 1]);
#pragma unroll
        for (int mt = 0; mt < 2; mt++)
#pragma unroll
            for (int half = 0; half < 2; half++) {
                int row = mbase + mt * 16 + g + half * 8;
#pragma unroll
                for (int cc = 0; cc < 2; cc++) {
                    float v = acc[mt][nt][half * 2 + cc] + (cc ? bv1 : bv0);
                    size_t idx = ((size_t)(b * C_ + o + cc) << 14) + p0 + row;
                    v += __ldg(&r1[idx]) + __ldg(&r2[idx]);
                    out[idx] = v;
                }
            }
    }
}

// ---------------- bf16 pipeline constants (attn/av, 256 thr, M-split 64) ----------------
#define BPAS 36
#define BAB_A (64 * BPAS)
#define BAB_B (128 * BPAS)
#define BPBUF (BAB_A + BAB_B)
#define BPIPE_SMEM_BYTES (2 * BPBUF * 4)

#define BPIPE_STAGE(sbuf32, Ap, Bp) do {                                         \
    _Pragma("unroll")                                                            \
    for (int r = 0; r < 2; r++) {                                                \
        int f = tid + 256 * r;                                                   \
        int row = f >> 3, c8 = f & 7;                                            \
        cpa16((sbuf32) + (row * BPAS + c8 * 4) * 4, (Ap) + row * 128 + c8 * 8);  \
    }                                                                            \
    _Pragma("unroll")                                                            \
    for (int r = 0; r < 4; r++) {                                                \
        int f = tid + 256 * r;                                                   \
        int row = f >> 3, c8 = f & 7;                                            \
        cpa16((sbuf32) + (BAB_A + row * BPAS + c8 * 4) * 4, (Bp) + row * 128 + c8 * 8); \
    }                                                                            \
    CP_COMMIT();                                                                 \
} while (0)

#define BPIPE_MMA(dA, dB, ACC) do {                                              \
    _Pragma("unroll")                                                            \
    for (int w = 0; w < 4; w++) {                                                \
        const int kp = w * 8 + tig;                                              \
        uint32_t a[2][4], bf[4][2];                                              \
        _Pragma("unroll")                                                        \
        for (int mt = 0; mt < 2; mt++) {                                         \
            int row = mbase + mt * 16 + g;                                       \
            a[mt][0] = (dA)[row * BPAS + kp];                                    \
            a[mt][1] = (dA)[(row + 8) * BPAS + kp];                              \
            a[mt][2] = (dA)[row * BPAS + kp + 4];                                \
            a[mt][3] = (dA)[(row + 8) * BPAS + kp + 4];                          \
        }                                                                        \
        _Pragma("unroll")                                                        \
        for (int nt = 0; nt < 4; nt++) {                                         \
            int col = nbase + nt * 8 + g;                                        \
            bf[nt][0] = (dB)[col * BPAS + kp];                                   \
            bf[nt][1] = (dB)[col * BPAS + kp + 4];                               \
        }                                                                        \
        _Pragma("unroll")                                                        \
        for (int mt = 0; mt < 2; mt++)                                           \
            _Pragma("unroll")                                                    \
            for (int nt = 0; nt < 4; nt++)                                       \
                mma_bf16(ACC[mt][nt], a[mt], bf[nt]);                            \
    }                                                                            \
} while (0)

// ---------------- attention: bf16 operands, fused softmax, bf16 output ----------------
__global__ __launch_bounds__(256, 2) void attn_mma_kernel(
    const __nv_bfloat16* __restrict__ o1b, const __nv_bfloat16* __restrict__ o2b,
    const __nv_bfloat16* __restrict__ o1tb, const __nv_bfloat16* __restrict__ o2tb,
    const float* __restrict__ n1h, const float* __restrict__ n2h,
    const float* __restrict__ n1w, const float* __restrict__ n2w,
    const float* __restrict__ pbh, const float* __restrict__ pbw,
    __nv_bfloat16* __restrict__ a1b, __nv_bfloat16* __restrict__ a2b)
{
    extern __shared__ float smf[];
    uint32_t* smu = (uint32_t*)smf;
    const uint32_t sbase = (uint32_t)__cvta_generic_to_shared(smf);
    const int bh = blockIdx.x;
    const int mode = blockIdx.y;
    const int mh = blockIdx.z;
    const int hd = bh & 7, b = bh >> 3;
    const int tid = threadIdx.x;
    const int lane = tid & 31, g = lane >> 2, tig = lane & 3;
    const int wid = tid >> 5;
    const int mbase = (wid & 1) * 32;
    const int nbase = (wid >> 1) * 32;
    const int mh64 = mh * 64;
    const __nv_bfloat16* Abase =
        ((mode ? o1tb : o2b) + ((size_t)b * C_ + hd * CPH_) * HW_) + mh64 * 128;
    const __nv_bfloat16* Bbase = (mode ? o2tb : o1b) + ((size_t)b * C_ + hd * CPH_) * HW_;

    float acc[2][4][4];
#pragma unroll
    for (int mt = 0; mt < 2; mt++)
#pragma unroll
        for (int nt = 0; nt < 4; nt++)
#pragma unroll
            for (int e = 0; e < 4; e++) acc[mt][nt][e] = 0.f;

    BPIPE_STAGE(sbase, Abase, Bbase);
    for (int kc = 0; kc < 48; kc++) {
        if (kc < 47) {
            int kn = kc + 1;
            const __nv_bfloat16* Ap = Abase + (kn >> 1) * HW_ + (kn & 1) * 64;
            const __nv_bfloat16* Bp = Bbase + (kn >> 1) * HW_ + (kn & 1) * 64;
            uint32_t sbuf = sbase + ((kn & 1) * BPBUF) * 4;
            BPIPE_STAGE(sbuf, Ap, Bp);
            CP_WAIT1();
        } else {
            CP_WAIT0();
        }
        __syncthreads();
        const uint32_t* dA = smu + (kc & 1) * BPBUF;
        const uint32_t* dB = dA + BAB_A;
        BPIPE_MMA(dA, dB, acc);
        __syncthreads();
    }

    const float* nI = mode ? n1w : n2h;
    const float* nJ = mode ? n2w : n1h;
    const float bias = mode ? __ldg(&pbw[hd]) : __ldg(&pbh[hd]);
    float rinv[4], cinv[8];
#pragma unroll
    for (int mt = 0; mt < 2; mt++)
#pragma unroll
        for (int half = 0; half < 2; half++) {
            int row = mbase + mt * 16 + g + half * 8;
            rinv[mt * 2 + half] =
                TEMP_INV / fmaxf(sqrtf(__ldg(&nI[bh * 128 + mh64 + row])), EPS_);
        }
#pragma unroll
    for (int nt = 0; nt < 4; nt++)
#pragma unroll
        for (int cc = 0; cc < 2; cc++) {
            int col = nbase + nt * 8 + 2 * tig + cc;
            cinv[nt * 2 + cc] = 1.f / fmaxf(sqrtf(__ldg(&nJ[bh * 128 + col])), EPS_);
        }
    float* sc = smf;
#pragma unroll
    for (int mt = 0; mt < 2; mt++)
#pragma unroll
        for (int half = 0; half < 2; half++) {
            int row = mbase + mt * 16 + g + half * 8;
            float ri = rinv[mt * 2 + half];
#pragma unroll
            for (int nt = 0; nt < 4; nt++) {
                int col = nbase + nt * 8 + 2 * tig;
                float2 v;
                v.x = acc[mt][nt][half * 2 + 0] * (ri * cinv[nt * 2 + 0]) + bias;
                v.y = acc[mt][nt][half * 2 + 1] * (ri * cinv[nt * 2 + 1]) + bias;
                *(float2*)&sc[row * 132 + col] = v;
            }
        }
    __syncthreads();

    __nv_bfloat16* outp = (mode ? a2b : a1b) + (size_t)bh * HW_ + mh64 * 128;
    for (int r = wid; r < 64; r += 8) {
        float4 v = *(float4*)&sc[r * 132 + lane * 4];
        float m = fmaxf(fmaxf(v.x, v.y), fmaxf(v.z, v.w));
#pragma unroll
        for (int s = 16; s >= 1; s >>= 1) m = fmaxf(m, __shfl_xor_sync(0xffffffffu, m, s));
        v.x = __expf(v.x - m); v.y = __expf(v.y - m);
        v.z = __expf(v.z - m); v.w = __expf(v.w - m);
        float su = v.x + v.y + v.z + v.w;
#pragma unroll
        for (int s = 16; s >= 1; s >>= 1) su += __shfl_xor_sync(0xffffffffu, su, s);
        float inv = 1.f / su;
        uint2 o;
        o.x = f2bf2(v.x * inv, v.y * inv);
        o.y = f2bf2(v.z * inv, v.w * inv);
        *(uint2*)&outp[r * 128 + lane * 4] = o;
    }
}

// ---------------- AV + q-residual + gated fusion: bf16 GEMMs, bf16 S reads ----------------
__global__ __launch_bounds__(256, 2) void av_mma_kernel(
    const __nv_bfloat16* __restrict__ o1b, const __nv_bfloat16* __restrict__ o2b,
    const __nv_bfloat16* __restrict__ o1tb,
    const __nv_bfloat16* __restrict__ a1b, const __nv_bfloat16* __restrict__ a2b,
    const float* __restrict__ n2h, const float* __restrict__ n1w,
    const float* __restrict__ gate, float* __restrict__ fus)
{
    extern __shared__ float smf[];
    uint32_t* smu = (uint32_t*)smf;
    const uint32_t sbase = (uint32_t)__cvta_generic_to_shared(smf);
    const int ch = blockIdx.x, b = blockIdx.y;
    const int mh = blockIdx.z;
    const int hd = ch / CPH_;
    const int bh = b * 8 + hd;
    const int tid = threadIdx.x;
    const int lane = tid & 31, g = lane >> 2, tig = lane & 3;
    const int wid = tid >> 5;
    const int mbase = (wid & 1) * 32;
    const int nbase = (wid >> 1) * 32;
    const int mh64 = mh * 64;

    const __nv_bfloat16* A1 = a1b + (size_t)bh * HW_ + mh64 * 128;
    const __nv_bfloat16* B1 = o1tb + ((size_t)b * C_ + ch) * HW_;
    const __nv_bfloat16* A2 = o2b + ((size_t)b * C_ + ch) * HW_ + mh64 * 128;
    const __nv_bfloat16* B2 = a2b + (size_t)bh * HW_;
    const __nv_bfloat16* S1 = o1b + ((size_t)b * C_ + ch) * HW_;
    const __nv_bfloat16* S2 = o2b + ((size_t)b * C_ + ch) * HW_;

    float acc1[2][4][4], acc2[2][4][4];
#pragma unroll
    for (int mt = 0; mt < 2; mt++)
#pragma unroll
        for (int nt = 0; nt < 4; nt++)
#pragma unroll
            for (int e = 0; e < 4; e++) { acc1[mt][nt][e] = 0.f; acc2[mt][nt][e] = 0.f; }

    const uint32_t sb0 = sbase;
    const uint32_t sb1 = sbase + BPBUF * 4;
    const uint32_t* dA0 = smu;
    const uint32_t* dB0 = smu + BAB_A;
    const uint32_t* dA1 = smu + BPBUF;
    const uint32_t* dB1 = smu + BPBUF + BAB_A;

    BPIPE_STAGE(sb0, A1, B1);
    BPIPE_STAGE(sb1, A1 + 64, B1 + 64);
    CP_WAIT1(); __syncthreads();
    BPIPE_MMA(dA0, dB0, acc1);
    __syncthreads();
    BPIPE_STAGE(sb0, A2, B2);
    CP_WAIT1(); __syncthreads();
    BPIPE_MMA(dA1, dB1, acc1);
    __syncthreads();
    BPIPE_STAGE(sb1, A2 + 64, B2 + 64);
    CP_WAIT1(); __syncthreads();
    BPIPE_MMA(dA0, dB0, acc2);
    CP_WAIT0(); __syncthreads();
    BPIPE_MMA(dA1, dB1, acc2);

    const float gg = 1.f / (1.f + expf(-__ldg(&gate[0])));
    float invy[4], invx[8];
#pragma unroll
    for (int mt = 0; mt < 2; mt++)
#pragma unroll
        for (int half = 0; half < 2; half++) {
            int row = mbase + mt * 16 + g + half * 8;
            invy[mt * 2 + half] =
                1.f / fmaxf(sqrtf(__ldg(&n2h[bh * 128 + mh64 + row])), EPS_);
        }
#pragma unroll
    for (int nt = 0; nt < 4; nt++)
#pragma unroll
        for (int cc = 0; cc < 2; cc++) {
            int col = nbase + nt * 8 + 2 * tig + cc;
            invx[nt * 2 + cc] = 1.f / fmaxf(sqrtf(__ldg(&n1w[bh * 128 + col])), EPS_);
        }

    float* fout = fus + ((size_t)b * C_ + ch) * HW_;
#pragma unroll
    for (int mt = 0; mt < 2; mt++)
#pragma unroll
        for (int half = 0; half < 2; half++) {
            int rl = mbase + mt * 16 + g + half * 8;
            int row = mh64 + rl;
            float iy = invy[mt * 2 + half];
#pragma unroll
            for (int nt = 0; nt < 4; nt++) {
                int col = nbase + nt * 8 + 2 * tig;
                float2 s1f = __bfloat1622float2(*(const __nv_bfloat162*)(S1 + row * 128 + col));
                float2 s2f = __bfloat1622float2(*(const __nv_bfloat162*)(S2 + row * 128 + col));
                float2 o;
                o.x = gg * (acc1[mt][nt][half * 2 + 0] + s2f.x * iy)
                    + (1.f - gg) * (acc2[mt][nt][half * 2 + 0] + s1f.x * invx[nt * 2 + 0]);
                o.y = gg * (acc1[mt][nt][half * 2 + 1] + s2f.y * iy)
                    + (1.f - gg) * (acc2[mt][nt][half * 2 + 1] + s1f.y * invx[nt * 2 + 1]);
                *(float2*)(fout + row * 128 + col) = o;
            }
        }
}

// ---------------- host launcher ----------------
extern "C" void kernel_launch(void* const* d_in, const int* in_sizes, int n_in,
                              void* d_out, int out_size)
{
    const float* x1  = (const float*)d_in[0];
    const float* x2  = (const float*)d_in[1];
    const float* Wp  = (const float*)d_in[2];
    const float* bp  = (const float*)d_in[3];
    const float* gate= (const float*)d_in[4];
    const float* pbh = (const float*)d_in[5];
    const float* pbw = (const float*)d_in[6];
    const float* Wm1 = (const float*)d_in[7];
    const float* bm1 = (const float*)d_in[8];
    const float* Wm2 = (const float*)d_in[9];
    const float* bm2 = (const float*)d_in[10];
    float* out = (float*)d_out;

    float *p_fus, *p_n1h, *p_n2h, *p_n1w, *p_n2w;
    __nv_bfloat16 *p_o1b, *p_o2b, *p_o1tb, *p_o2tb, *p_a1b, *p_a2b;
    cudaGetSymbolAddress((void**)&p_fus, g_fus);
    cudaGetSymbolAddress((void**)&p_o1b, g_o1b);
    cudaGetSymbolAddress((void**)&p_o2b, g_o2b);
    cudaGetSymbolAddress((void**)&p_o1tb, g_o1tb);
    cudaGetSymbolAddress((void**)&p_o2tb, g_o2tb);
    cudaGetSymbolAddress((void**)&p_a1b, g_a1b);
    cudaGetSymbolAddress((void**)&p_a2b, g_a2b);
    cudaGetSymbolAddress((void**)&p_n1h, g_n1h);
    cudaGetSymbolAddress((void**)&p_n2h, g_n2h);
    cudaGetSymbolAddress((void**)&p_n1w, g_n1w);
    cudaGetSymbolAddress((void**)&p_n2w, g_n2w);

    cudaFuncSetAttribute(conv_front_kernel, cudaFuncAttributeMaxDynamicSharedMemorySize, SMEM_BYTES);
    cudaFuncSetAttribute(conv3x_kernel, cudaFuncAttributeMaxDynamicSharedMemorySize, C3_SMEM_BYTES);
    cudaFuncSetAttribute(attn_mma_kernel, cudaFuncAttributeMaxDynamicSharedMemorySize, BPIPE_SMEM_BYTES);
    cudaFuncSetAttribute(av_mma_kernel, cudaFuncAttributeMaxDynamicSharedMemorySize, BPIPE_SMEM_BYTES);

    norm_init_kernel<<<32, 256>>>(p_n1h, p_n1w, p_n2h, p_n2w);

    conv_front_kernel<<<dim3(NTILES_, 2), 512, SMEM_BYTES>>>(
        x1, x2, Wp, bp, p_o1b, p_o2b, p_n1h, p_n1w, p_n2h, p_n2w);

    repackT_kernel<<<dim3(4, 2 * C_, B_), 256>>>(p_o1b, p_o2b, p_o1tb, p_o2tb);

    attn_mma_kernel<<<dim3(B_ * HEADS_, 2, 2), 256, BPIPE_SMEM_BYTES>>>(
        p_o1b, p_o2b, p_o1tb, p_o2tb, p_n1h, p_n2h, p_n1w, p_n2w, pbh, pbw, p_a1b, p_a2b);

    av_mma_kernel<<<dim3(C_, B_, 2), 256, BPIPE_SMEM_BYTES>>>(
        p_o1b, p_o2b, p_o1tb, p_a1b, p_a2b, p_n2h, p_n1w, gate, p_fus);

    conv3x_kernel<<<NTILES_, 512, C3_SMEM_BYTES>>>(p_fus, Wp, bp, Wm1, bm1, Wm2, bm2,
                                                   x1, x2, out);

    (void)in_sizes; (void)n_in; (void)out_size;
}

// round 16
// speedup vs baseline: 1.7390x; 1.0278x over previous
#include <cuda_runtime.h>
#include <cuda_bf16.h>
#include <math.h>
#include <stdint.h>

#define B_ 8
#define C_ 192
#define H_ 128
#define W_ 128
#define HW_ 16384
#define HEADS_ 8
#define CPH_ 24
#define TEMP_INV 100.0f
#define EPS_ 1e-12f

#define NPIX_ (B_ * HW_)
#define NTILES_ (NPIX_ / 128)

// ---------------- scratch ----------------
__device__ __nv_bfloat16 g_fus[(size_t)B_ * C_ * HW_];   // fusion, bf16
__device__ __nv_bfloat16 g_o1b[(size_t)B_ * C_ * HW_];   // [y][x] bf16
__device__ __nv_bfloat16 g_o2b[(size_t)B_ * C_ * HW_];
__device__ __nv_bfloat16 g_o1tb[(size_t)B_ * C_ * HW_];  // [x][y] bf16
__device__ __nv_bfloat16 g_o2tb[(size_t)B_ * C_ * HW_];
__device__ __nv_bfloat16 g_a1b[(size_t)B_ * HEADS_ * HW_];
__device__ __nv_bfloat16 g_a2b[(size_t)B_ * HEADS_ * HW_];
__device__ float g_n1h[B_ * HEADS_ * H_];   // squared sums (sqrt at consumer)
__device__ float g_n2h[B_ * HEADS_ * H_];
__device__ float g_n1w[B_ * HEADS_ * W_];
__device__ float g_n2w[B_ * HEADS_ * W_];

__device__ __forceinline__ float to_tf32(float x) {
    uint32_t u; asm("cvt.rna.tf32.f32 %0, %1;" : "=r"(u) : "f"(x));
    return __uint_as_float(u);
}
__device__ __forceinline__ float4 to_tf32_4(float4 v) {
    v.x = to_tf32(v.x); v.y = to_tf32(v.y); v.z = to_tf32(v.z); v.w = to_tf32(v.w);
    return v;
}
__device__ __forceinline__ uint32_t f2bf2(float a, float b) {
    __nv_bfloat162 h = __floats2bfloat162_rn(a, b);
    return *(uint32_t*)&h;
}

__device__ __forceinline__ void mma_tf32(float* c, const uint32_t* a, const uint32_t* b) {
    asm volatile(
        "mma.sync.aligned.m16n8k8.row.col.f32.tf32.tf32.f32 "
        "{%0,%1,%2,%3}, {%4,%5,%6,%7}, {%8,%9}, {%0,%1,%2,%3};"
        : "+f"(c[0]), "+f"(c[1]), "+f"(c[2]), "+f"(c[3])
        : "r"(a[0]), "r"(a[1]), "r"(a[2]), "r"(a[3]), "r"(b[0]), "r"(b[1]));
}
__device__ __forceinline__ void mma_bf16(float* c, const uint32_t* a, const uint32_t* b) {
    asm volatile(
        "mma.sync.aligned.m16n8k16.row.col.f32.bf16.bf16.f32 "
        "{%0,%1,%2,%3}, {%4,%5,%6,%7}, {%8,%9}, {%0,%1,%2,%3};"
        : "+f"(c[0]), "+f"(c[1]), "+f"(c[2]), "+f"(c[3])
        : "r"(a[0]), "r"(a[1]), "r"(a[2]), "r"(a[3]), "r"(b[0]), "r"(b[1]));
}

__device__ __forceinline__ void cpa16(uint32_t s, const void* g) {
    asm volatile("cp.async.cg.shared.global [%0], [%1], 16;" :: "r"(s), "l"(g));
}
#define CP_COMMIT() asm volatile("cp.async.commit_group;" ::: "memory")
#define CP_WAIT1()  asm volatile("cp.async.wait_group 1;" ::: "memory")
#define CP_WAIT0()  asm volatile("cp.async.wait_group 0;" ::: "memory")

__global__ void norm_init_kernel(float* a, float* b, float* c, float* d) {
    int i = blockIdx.x * 256 + threadIdx.x;
    if (i < B_ * HEADS_ * 128) { a[i] = 0.f; b[i] = 0.f; c[i] = 0.f; d[i] = 0.f; }
}

// ---------------- conv1x1 front: fp32 channel-first in -> bf16 channel-first out + norms ----
#define SAS 36
#define ATS 136
#define CONV_ATBUF (32 * ATS)
#define CONV_WBUF (192 * SAS)
#define SMEM_BYTES ((2 * CONV_ATBUF + 2 * CONV_WBUF) * 4)
#define SBF_STRIDE 132
#define SPART_FOFF ((192 * SBF_STRIDE) / 2)

__global__ __launch_bounds__(512, 1) void conv_front_kernel(
    const float* __restrict__ x1, const float* __restrict__ x2,
    const float* __restrict__ Wt, const float* __restrict__ bias,
    __nv_bfloat16* __restrict__ o1b, __nv_bfloat16* __restrict__ o2b,
    float* __restrict__ n1h, float* __restrict__ n1w,
    float* __restrict__ n2h, float* __restrict__ n2w)
{
    extern __shared__ float sm[];
    const int tid = threadIdx.x;
    const int lane = tid & 31;
    const int g = lane >> 2;
    const int tig = lane & 3;
    const int wid = tid >> 5;
    const int mbase = (wid & 3) * 32;
    const int nbase = (wid >> 2) * 48;
    const int h0 = nbase / 24;
    const int t = blockIdx.x;
    const int pg0 = t << 7;
    const int b = pg0 >> 14;
    const int p0 = pg0 & (HW_ - 1);
    const float* inb = (blockIdx.y ? x2 : x1) + (size_t)b * C_ * HW_;

    float c[2][6][4];
#pragma unroll
    for (int mt = 0; mt < 2; mt++)
#pragma unroll
        for (int nt = 0; nt < 6; nt++)
#pragma unroll
            for (int r = 0; r < 4; r++) c[mt][nt][r] = 0.f;

    float4 pa[2], pw[3];
#pragma unroll
    for (int r = 0; r < 2; r++) {
        int f = tid + 512 * r;
        pa[r] = *(const float4*)(inb + (size_t)(f >> 5) * HW_ + p0 + (f & 31) * 4);
    }
#pragma unroll
    for (int r = 0; r < 3; r++) {
        int f = tid + 512 * r;
        pw[r] = *(const float4*)(Wt + (size_t)(f >> 3) * C_ + (f & 7) * 4);
    }

    for (int kc = 0; kc < 6; kc++) {
        float* dA = sm + (kc & 1) * CONV_ATBUF;
        float* dW = sm + 2 * CONV_ATBUF + (kc & 1) * CONV_WBUF;
#pragma unroll
        for (int r = 0; r < 2; r++) {
            int f = tid + 512 * r;
            *(float4*)&dA[(f >> 5) * ATS + (f & 31) * 4] = to_tf32_4(pa[r]);
        }
#pragma unroll
        for (int r = 0; r < 3; r++) {
            int f = tid + 512 * r;
            *(float4*)&dW[(f >> 3) * SAS + (f & 7) * 4] = to_tf32_4(pw[r]);
        }
        __syncthreads();
        if (kc < 5) {
            int ko = (kc + 1) * 32;
#pragma unroll
            for (int r = 0; r < 2; r++) {
                int f = tid + 512 * r;
                pa[r] = *(const float4*)(inb + (size_t)(ko + (f >> 5)) * HW_ + p0 + (f & 31) * 4);
            }
#pragma unroll
            for (int r = 0; r < 3; r++) {
                int f = tid + 512 * r;
                pw[r] = *(const float4*)(Wt + (size_t)(f >> 3) * C_ + ko + (f & 7) * 4);
            }
        }
#pragma unroll
        for (int kk = 0; kk < 4; kk++) {
            const int k0 = kk * 8 + tig;
            uint32_t a[2][4], bb[6][2];
#pragma unroll
            for (int mt = 0; mt < 2; mt++) {
                int row = mbase + mt * 16 + g;
                a[mt][0] = __float_as_uint(dA[k0 * ATS + row]);
                a[mt][1] = __float_as_uint(dA[k0 * ATS + row + 8]);
                a[mt][2] = __float_as_uint(dA[(k0 + 4) * ATS + row]);
                a[mt][3] = __float_as_uint(dA[(k0 + 4) * ATS + row + 8]);
            }
#pragma unroll
            for (int nt = 0; nt < 6; nt++) {
                int col = nbase + nt * 8 + g;
                bb[nt][0] = __float_as_uint(dW[col * SAS + k0]);
                bb[nt][1] = __float_as_uint(dW[col * SAS + k0 + 4]);
            }
#pragma unroll
            for (int mt = 0; mt < 2; mt++)
#pragma unroll
                for (int nt = 0; nt < 6; nt++)
                    mma_tf32(c[mt][nt], a[mt], bb[nt]);
        }
    }
    __syncthreads();

    __nv_bfloat16* sBF = (__nv_bfloat16*)sm;
    float* spart = sm + SPART_FOFF;
#pragma unroll
    for (int i = tid; i < 128 * 8; i += 512) spart[i] = 0.f;
    __syncthreads();

    float bv[6][2];
#pragma unroll
    for (int nt = 0; nt < 6; nt++) {
        int o = nbase + nt * 8 + 2 * tig;
        bv[nt][0] = __ldg(&bias[o]);
        bv[nt][1] = __ldg(&bias[o + 1]);
    }

#pragma unroll
    for (int mt = 0; mt < 2; mt++)
#pragma unroll
        for (int half = 0; half < 2; half++) {
            int row = mbase + mt * 16 + g + half * 8;
            float s0 = 0.f, s1 = 0.f;
#pragma unroll
            for (int nt = 0; nt < 6; nt++) {
                int o = nbase + nt * 8 + 2 * tig;
                float v0 = c[mt][nt][half * 2 + 0] + bv[nt][0];
                float v1 = c[mt][nt][half * 2 + 1] + bv[nt][1];
                sBF[o * SBF_STRIDE + row] = __float2bfloat16_rn(v0);
                sBF[(o + 1) * SBF_STRIDE + row] = __float2bfloat16_rn(v1);
                float sq = v0 * v0 + v1 * v1;
                if (nt < 3) s0 += sq; else s1 += sq;
            }
            s0 += __shfl_xor_sync(0xffffffffu, s0, 1);
            s0 += __shfl_xor_sync(0xffffffffu, s0, 2);
            s1 += __shfl_xor_sync(0xffffffffu, s1, 1);
            s1 += __shfl_xor_sync(0xffffffffu, s1, 2);
            if (tig == 0) {
                atomicAdd(&spart[row * 8 + h0], s0);
                atomicAdd(&spart[row * 8 + h0 + 1], s1);
            }
        }
    __syncthreads();

    __nv_bfloat16* outp = (blockIdx.y ? o2b : o1b);
#pragma unroll
    for (int r = 0; r < 24; r++) {
        int f = tid + 512 * r;
        int cch = f >> 6, xu = f & 63;
        uint32_t u = *(uint32_t*)&sBF[cch * SBF_STRIDE + 2 * xu];
        *(uint32_t*)&outp[((size_t)(b * C_ + cch) << 14) + p0 + 2 * xu] = u;
    }

    float* rowAcc = blockIdx.y ? n2h : n1h;
    float* colAcc = blockIdx.y ? n2w : n1w;
    const int y = p0 >> 7;
    if (tid < 256) {
        int head = tid >> 5, l = tid & 31;
        float s = spart[l * 8 + head] + spart[(l + 32) * 8 + head]
                + spart[(l + 64) * 8 + head] + spart[(l + 96) * 8 + head];
#pragma unroll
        for (int sh = 16; sh >= 1; sh >>= 1) s += __shfl_xor_sync(0xffffffffu, s, sh);
        if (l == 0) rowAcc[(b * 8 + head) * 128 + y] = s;
    }
#pragma unroll
    for (int r = 0; r < 2; r++) {
        int f = tid + 512 * r;
        int x = f >> 3, head = f & 7;
        atomicAdd(&colAcc[(b * 8 + head) * 128 + x], spart[x * 8 + head]);
    }
}

// ---------------- slim repack: bf16 [y][x] -> bf16 [x][y], 64x64 tiles ----------------
__global__ __launch_bounds__(256) void repackT_kernel(
    const __nv_bfloat16* __restrict__ o1b, const __nv_bfloat16* __restrict__ o2b,
    __nv_bfloat16* __restrict__ o1tb, __nv_bfloat16* __restrict__ o2tb)
{
    __shared__ __nv_bfloat16 t[64][66];
    const int cy = blockIdx.y;
    const int src = cy >= C_;
    const int c = src ? cy - C_ : cy;
    const int b = blockIdx.z;
    const int x0 = (blockIdx.x & 1) * 64, y0 = (blockIdx.x >> 1) * 64;
    const int tid = threadIdx.x;
    const __nv_bfloat16* ib = (src ? o2b : o1b) + ((size_t)b * C_ + c) * HW_;
    __nv_bfloat16* ob = (src ? o2tb : o1tb) + ((size_t)b * C_ + c) * HW_;
#pragma unroll
    for (int r = 0; r < 8; r++) {
        int f = tid + 256 * r;
        int row = f >> 5, xu = f & 31;
        uint32_t u = *(const uint32_t*)&ib[(y0 + row) * 128 + x0 + 2 * xu];
        __nv_bfloat162 h2 = *(__nv_bfloat162*)&u;
        t[2 * xu][row] = h2.x;
        t[2 * xu + 1][row] = h2.y;
    }
    __syncthreads();
#pragma unroll
    for (int r = 0; r < 8; r++) {
        int f = tid + 256 * r;
        int xr = f >> 5, yu = f & 31;
        uint32_t u = *(uint32_t*)&t[xr][2 * yu];
        *(uint32_t*)&ob[(x0 + xr) * 128 + y0 + 2 * yu] = u;
    }
}

// ---------------- fused triple conv (bf16 fus in, fp32 out) ----------------
#define C3_SO_STRIDE 196
#define C3_SO_FLOATS (128 * C3_SO_STRIDE)
#define C3_W_OFF C3_SO_FLOATS
#define C3_SMEM_BYTES ((C3_SO_FLOATS + 2 * CONV_WBUF) * 4)

#define C3_MMALOOP_SO(kbase, dWpt, ACC) do {                                     \
    _Pragma("unroll")                                                            \
    for (int kk = 0; kk < 4; kk++) {                                             \
        const int k0 = kk * 8 + tig;                                             \
        uint32_t a[2][4], bb[6][2];                                              \
        _Pragma("unroll")                                                        \
        for (int mt = 0; mt < 2; mt++) {                                         \
            int row = mbase + mt * 16 + g;                                       \
            a[mt][0] = __float_as_uint(sO[row * C3_SO_STRIDE + (kbase) + k0]);   \
            a[mt][1] = __float_as_uint(sO[(row + 8) * C3_SO_STRIDE + (kbase) + k0]); \
            a[mt][2] = __float_as_uint(sO[row * C3_SO_STRIDE + (kbase) + k0 + 4]); \
            a[mt][3] = __float_as_uint(sO[(row + 8) * C3_SO_STRIDE + (kbase) + k0 + 4]); \
        }                                                                        \
        _Pragma("unroll")                                                        \
        for (int nt = 0; nt < 6; nt++) {                                         \
            int col = nbase + nt * 8 + g;                                        \
            bb[nt][0] = __float_as_uint((dWpt)[col * SAS + k0]);                 \
            bb[nt][1] = __float_as_uint((dWpt)[col * SAS + k0 + 4]);             \
        }                                                                        \
        _Pragma("unroll")                                                        \
        for (int mt = 0; mt < 2; mt++)                                           \
            _Pragma("unroll")                                                    \
            for (int nt = 0; nt < 6; nt++)                                       \
                mma_tf32(ACC[mt][nt], a[mt], bb[nt]);                            \
    }                                                                            \
} while (0)

#define C3_LOADW(Wsrc, ko) do {                                                  \
    _Pragma("unroll")                                                            \
    for (int r = 0; r < 3; r++) {                                                \
        int f = tid + 512 * r;                                                   \
        pw[r] = *(const float4*)((Wsrc) + (size_t)(f >> 3) * C_ + (ko) + (f & 7) * 4); \
    }                                                                            \
} while (0)

#define C3_STOREW(dWpt) do {                                                     \
    _Pragma("unroll")                                                            \
    for (int r = 0; r < 3; r++) {                                                \
        int f = tid + 512 * r;                                                   \
        *(float4*)&(dWpt)[(f >> 3) * SAS + (f & 7) * 4] = to_tf32_4(pw[r]);      \
    }                                                                            \
} while (0)

#define C3_ZEROACC(ACC) do {                                                     \
    _Pragma("unroll")                                                            \
    for (int mt = 0; mt < 2; mt++)                                               \
        _Pragma("unroll")                                                        \
        for (int nt = 0; nt < 6; nt++)                                           \
            _Pragma("unroll")                                                    \
            for (int r = 0; r < 4; r++) ACC[mt][nt][r] = 0.f;                    \
} while (0)

#define C3_EPI_SMEM(ACC, biasp, do_gelu) do {                                    \
    _Pragma("unroll")                                                            \
    for (int nt = 0; nt < 6; nt++) {                                             \
        int o = nbase + nt * 8 + 2 * tig;                                        \
        float bv0 = __ldg(&(biasp)[o]);                                          \
        float bv1 = __ldg(&(biasp)[o + 1]);                                      \
        _Pragma("unroll")                                                        \
        for (int mt = 0; mt < 2; mt++)                                           \
            _Pragma("unroll")                                                    \
            for (int half = 0; half < 2; half++) {                               \
                int row = mbase + mt * 16 + g + half * 8;                        \
                float v0 = ACC[mt][nt][half * 2 + 0] + bv0;                      \
                float v1 = ACC[mt][nt][half * 2 + 1] + bv1;                      \
                if (do_gelu) {                                                   \
                    v0 = 0.5f * v0 * (1.0f + erff(v0 * 0.70710678118654752f));   \
                    v1 = 0.5f * v1 * (1.0f + erff(v1 * 0.70710678118654752f));   \
                }                                                                \
                float2 w = {to_tf32(v0), to_tf32(v1)};                           \
                *(float2*)&sO[row * C3_SO_STRIDE + o] = w;                       \
            }                                                                    \
    }                                                                            \
} while (0)

__global__ __launch_bounds__(512, 1) void conv3x_kernel(
    const __nv_bfloat16* __restrict__ fus,
    const float* __restrict__ Wp,  const float* __restrict__ bp,
    const float* __restrict__ Wm1, const float* __restrict__ bm1,
    const float* __restrict__ Wm2, const float* __restrict__ bm2,
    const float* __restrict__ r1,  const float* __restrict__ r2,
    float* __restrict__ out)
{
    extern __shared__ float sm[];
    float* sO = sm;
    float* sW = sm + C3_W_OFF;
    const int tid = threadIdx.x;
    const int lane = tid & 31;
    const int g = lane >> 2;
    const int tig = lane & 3;
    const int wid = tid >> 5;
    const int mbase = (wid & 3) * 32;
    const int nbase = (wid >> 2) * 48;
    const int t = blockIdx.x;
    const int pg0 = t << 7;
    const int b = pg0 >> 14;
    const int p0 = pg0 & (HW_ - 1);
    const __nv_bfloat16* inb = fus + (size_t)b * C_ * HW_;

    float acc[2][6][4];
    float4 pw[3];
    uint4 pa16;

    // ---------- GEMM1: bf16 A staged (one uint4 = 8 bf16 per thread per chunk) ----------
    C3_ZEROACC(acc);
    pa16 = *(const uint4*)(inb + (size_t)(tid >> 4) * HW_ + p0 + (tid & 15) * 8);
    C3_LOADW(Wp, 0);
    for (int kc = 0; kc < 6; kc++) {
        float* dA = sm + (kc & 1) * CONV_ATBUF;
        float* dW = sW + (kc & 1) * CONV_WBUF;
        {
            const __nv_bfloat162* hp = (const __nv_bfloat162*)&pa16;
            int row = tid >> 4, cx = (tid & 15) * 8;
            float2 f0 = __bfloat1622float2(hp[0]);
            float2 f1 = __bfloat1622float2(hp[1]);
            float2 f2 = __bfloat1622float2(hp[2]);
            float2 f3 = __bfloat1622float2(hp[3]);
            float4 w0 = {f0.x, f0.y, f1.x, f1.y};
            float4 w1 = {f2.x, f2.y, f3.x, f3.y};
            *(float4*)&dA[row * ATS + cx] = w0;
            *(float4*)&dA[row * ATS + cx + 4] = w1;
        }
        C3_STOREW(dW);
        __syncthreads();
        if (kc < 5) {
            int ko = (kc + 1) * 32;
            pa16 = *(const uint4*)(inb + (size_t)(ko + (tid >> 4)) * HW_ + p0 + (tid & 15) * 8);
            C3_LOADW(Wp, ko);
        }
#pragma unroll
        for (int kk = 0; kk < 4; kk++) {
            const int k0 = kk * 8 + tig;
            uint32_t a[2][4], bb[6][2];
#pragma unroll
            for (int mt = 0; mt < 2; mt++) {
                int row = mbase + mt * 16 + g;
                a[mt][0] = __float_as_uint(dA[k0 * ATS + row]);
                a[mt][1] = __float_as_uint(dA[k0 * ATS + row + 8]);
                a[mt][2] = __float_as_uint(dA[(k0 + 4) * ATS + row]);
                a[mt][3] = __float_as_uint(dA[(k0 + 4) * ATS + row + 8]);
            }
#pragma unroll
            for (int nt = 0; nt < 6; nt++) {
                int col = nbase + nt * 8 + g;
                bb[nt][0] = __float_as_uint(dW[col * SAS + k0]);
                bb[nt][1] = __float_as_uint(dW[col * SAS + k0 + 4]);
            }
#pragma unroll
            for (int mt = 0; mt < 2; mt++)
#pragma unroll
                for (int nt = 0; nt < 6; nt++)
                    mma_tf32(acc[mt][nt], a[mt], bb[nt]);
        }
    }
    __syncthreads();
    C3_EPI_SMEM(acc, bp, 0);
    __syncthreads();

    C3_ZEROACC(acc);
    C3_LOADW(Wm1, 0);
    for (int kc = 0; kc < 6; kc++) {
        float* dW = sW + (kc & 1) * CONV_WBUF;
        C3_STOREW(dW);
        __syncthreads();
        if (kc < 5) C3_LOADW(Wm1, (kc + 1) * 32);
        C3_MMALOOP_SO(kc * 32, dW, acc);
    }
    __syncthreads();
    C3_EPI_SMEM(acc, bm1, 1);
    __syncthreads();

    C3_ZEROACC(acc);
    C3_LOADW(Wm2, 0);
    for (int kc = 0; kc < 6; kc++) {
        float* dW = sW + (kc & 1) * CONV_WBUF;
        C3_STOREW(dW);
        __syncthreads();
        if (kc < 5) C3_LOADW(Wm2, (kc + 1) * 32);
        C3_MMALOOP_SO(kc * 32, dW, acc);
    }

#pragma unroll
    for (int nt = 0; nt < 6; nt++) {
        int o = nbase + nt * 8 + 2 * tig;
        float bv0 = __ldg(&bm2[o]);
        float bv1 = __ldg(&bm2[o + 1]);
#pragma unroll
        for (int mt = 0; mt < 2; mt++)
#pragma unroll
            for (int half = 0; half < 2; half++) {
                int row = mbase + mt * 16 + g + half * 8;
#pragma unroll
                for (int cc = 0; cc < 2; cc++) {
                    float v = acc[mt][nt][half * 2 + cc] + (cc ? bv1 : bv0);
                    size_t idx = ((size_t)(b * C_ + o + cc) << 14) + p0 + row;
                    v += __ldg(&r1[idx]) + __ldg(&r2[idx]);
                    out[idx] = v;
                }
            }
    }
}

// ---------------- bf16 pipeline constants (attn/av, 256 thr, M-split 64) ----------------
#define BPAS 36
#define BAB_A (64 * BPAS)
#define BAB_B (128 * BPAS)
#define BPBUF (BAB_A + BAB_B)
#define BPIPE_SMEM_BYTES (2 * BPBUF * 4)

#define BPIPE_STAGE(sbuf32, Ap, Bp) do {                                         \
    _Pragma("unroll")                                                            \
    for (int r = 0; r < 2; r++) {                                                \
        int f = tid + 256 * r;                                                   \
        int row = f >> 3, c8 = f & 7;                                            \
        cpa16((sbuf32) + (row * BPAS + c8 * 4) * 4, (Ap) + row * 128 + c8 * 8);  \
    }                                                                            \
    _Pragma("unroll")                                                            \
    for (int r = 0; r < 4; r++) {                                                \
        int f = tid + 256 * r;                                                   \
        int row = f >> 3, c8 = f & 7;                                            \
        cpa16((sbuf32) + (BAB_A + row * BPAS + c8 * 4) * 4, (Bp) + row * 128 + c8 * 8); \
    }                                                                            \
    CP_COMMIT();                                                                 \
} while (0)

#define BPIPE_MMA(dA, dB, ACC) do {                                              \
    _Pragma("unroll")                                                            \
    for (int w = 0; w < 4; w++) {                                                \
        const int kp = w * 8 + tig;                                              \
        uint32_t a[2][4], bf[4][2];                                              \
        _Pragma("unroll")                                                        \
        for (int mt = 0; mt < 2; mt++) {                                         \
            int row = mbase + mt * 16 + g;                                       \
            a[mt][0] = (dA)[row * BPAS + kp];                                    \
            a[mt][1] = (dA)[(row + 8) * BPAS + kp];                              \
            a[mt][2] = (dA)[row * BPAS + kp + 4];                                \
            a[mt][3] = (dA)[(row + 8) * BPAS + kp + 4];                          \
        }                                                                        \
        _Pragma("unroll")                                                        \
        for (int nt = 0; nt < 4; nt++) {                                         \
            int col = nbase + nt * 8 + g;                                        \
            bf[nt][0] = (dB)[col * BPAS + kp];                                   \
            bf[nt][1] = (dB)[col * BPAS + kp + 4];                               \
        }                                                                        \
        _Pragma("unroll")                                                        \
        for (int mt = 0; mt < 2; mt++)                                           \
            _Pragma("unroll")                                                    \
            for (int nt = 0; nt < 4; nt++)                                       \
                mma_bf16(ACC[mt][nt], a[mt], bf[nt]);                            \
    }                                                                            \
} while (0)

// ---------------- attention: bf16 operands, fused softmax, bf16 output ----------------
__global__ __launch_bounds__(256, 2) void attn_mma_kernel(
    const __nv_bfloat16* __restrict__ o1b, const __nv_bfloat16* __restrict__ o2b,
    const __nv_bfloat16* __restrict__ o1tb, const __nv_bfloat16* __restrict__ o2tb,
    const float* __restrict__ n1h, const float* __restrict__ n2h,
    const float* __restrict__ n1w, const float* __restrict__ n2w,
    const float* __restrict__ pbh, const float* __restrict__ pbw,
    __nv_bfloat16* __restrict__ a1b, __nv_bfloat16* __restrict__ a2b)
{
    extern __shared__ float smf[];
    uint32_t* smu = (uint32_t*)smf;
    const uint32_t sbase = (uint32_t)__cvta_generic_to_shared(smf);
    const int bh = blockIdx.x;
    const int mode = blockIdx.y;
    const int mh = blockIdx.z;
    const int hd = bh & 7, b = bh >> 3;
    const int tid = threadIdx.x;
    const int lane = tid & 31, g = lane >> 2, tig = lane & 3;
    const int wid = tid >> 5;
    const int mbase = (wid & 1) * 32;
    const int nbase = (wid >> 1) * 32;
    const int mh64 = mh * 64;
    const __nv_bfloat16* Abase =
        ((mode ? o1tb : o2b) + ((size_t)b * C_ + hd * CPH_) * HW_) + mh64 * 128;
    const __nv_bfloat16* Bbase = (mode ? o2tb : o1b) + ((size_t)b * C_ + hd * CPH_) * HW_;

    float acc[2][4][4];
#pragma unroll
    for (int mt = 0; mt < 2; mt++)
#pragma unroll
        for (int nt = 0; nt < 4; nt++)
#pragma unroll
            for (int e = 0; e < 4; e++) acc[mt][nt][e] = 0.f;

    BPIPE_STAGE(sbase, Abase, Bbase);
    for (int kc = 0; kc < 48; kc++) {
        if (kc < 47) {
            int kn = kc + 1;
            const __nv_bfloat16* Ap = Abase + (kn >> 1) * HW_ + (kn & 1) * 64;
            const __nv_bfloat16* Bp = Bbase + (kn >> 1) * HW_ + (kn & 1) * 64;
            uint32_t sbuf = sbase + ((kn & 1) * BPBUF) * 4;
            BPIPE_STAGE(sbuf, Ap, Bp);
            CP_WAIT1();
        } else {
            CP_WAIT0();
        }
        __syncthreads();
        const uint32_t* dA = smu + (kc & 1) * BPBUF;
        const uint32_t* dB = dA + BAB_A;
        BPIPE_MMA(dA, dB, acc);
        __syncthreads();
    }

    const float* nI = mode ? n1w : n2h;
    const float* nJ = mode ? n2w : n1h;
    const float bias = mode ? __ldg(&pbw[hd]) : __ldg(&pbh[hd]);
    float rinv[4], cinv[8];
#pragma unroll
    for (int mt = 0; mt < 2; mt++)
#pragma unroll
        for (int half = 0; half < 2; half++) {
            int row = mbase + mt * 16 + g + half * 8;
            rinv[mt * 2 + half] =
                TEMP_INV / fmaxf(sqrtf(__ldg(&nI[bh * 128 + mh64 + row])), EPS_);
        }
#pragma unroll
    for (int nt = 0; nt < 4; nt++)
#pragma unroll
        for (int cc = 0; cc < 2; cc++) {
            int col = nbase + nt * 8 + 2 * tig + cc;
            cinv[nt * 2 + cc] = 1.f / fmaxf(sqrtf(__ldg(&nJ[bh * 128 + col])), EPS_);
        }
    float* sc = smf;
#pragma unroll
    for (int mt = 0; mt < 2; mt++)
#pragma unroll
        for (int half = 0; half < 2; half++) {
            int row = mbase + mt * 16 + g + half * 8;
            float ri = rinv[mt * 2 + half];
#pragma unroll
            for (int nt = 0; nt < 4; nt++) {
                int col = nbase + nt * 8 + 2 * tig;
                float2 v;
                v.x = acc[mt][nt][half * 2 + 0] * (ri * cinv[nt * 2 + 0]) + bias;
                v.y = acc[mt][nt][half * 2 + 1] * (ri * cinv[nt * 2 + 1]) + bias;
                *(float2*)&sc[row * 132 + col] = v;
            }
        }
    __syncthreads();

    __nv_bfloat16* outp = (mode ? a2b : a1b) + (size_t)bh * HW_ + mh64 * 128;
    for (int r = wid; r < 64; r += 8) {
        float4 v = *(float4*)&sc[r * 132 + lane * 4];
        float m = fmaxf(fmaxf(v.x, v.y), fmaxf(v.z, v.w));
#pragma unroll
        for (int s = 16; s >= 1; s >>= 1) m = fmaxf(m, __shfl_xor_sync(0xffffffffu, m, s));
        v.x = __expf(v.x - m); v.y = __expf(v.y - m);
        v.z = __expf(v.z - m); v.w = __expf(v.w - m);
        float su = v.x + v.y + v.z + v.w;
#pragma unroll
        for (int s = 16; s >= 1; s >>= 1) su += __shfl_xor_sync(0xffffffffu, su, s);
        float inv = 1.f / su;
        uint2 o;
        o.x = f2bf2(v.x * inv, v.y * inv);
        o.y = f2bf2(v.z * inv, v.w * inv);
        *(uint2*)&outp[r * 128 + lane * 4] = o;
    }
}

// ---------------- AV + q-residual + gated fusion: bf16 in, bf16 fus out ----------------
__global__ __launch_bounds__(256, 2) void av_mma_kernel(
    const __nv_bfloat16* __restrict__ o1b, const __nv_bfloat16* __restrict__ o2b,
    const __nv_bfloat16* __restrict__ o1tb,
    const __nv_bfloat16* __restrict__ a1b, const __nv_bfloat16* __restrict__ a2b,
    const float* __restrict__ n2h, const float* __restrict__ n1w,
    const float* __restrict__ gate, __nv_bfloat16* __restrict__ fus)
{
    extern __shared__ float smf[];
    uint32_t* smu = (uint32_t*)smf;
    const uint32_t sbase = (uint32_t)__cvta_generic_to_shared(smf);
    const int ch = blockIdx.x, b = blockIdx.y;
    const int mh = blockIdx.z;
    const int hd = ch / CPH_;
    const int bh = b * 8 + hd;
    const int tid = threadIdx.x;
    const int lane = tid & 31, g = lane >> 2, tig = lane & 3;
    const int wid = tid >> 5;
    const int mbase = (wid & 1) * 32;
    const int nbase = (wid >> 1) * 32;
    const int mh64 = mh * 64;

    const __nv_bfloat16* A1 = a1b + (size_t)bh * HW_ + mh64 * 128;
    const __nv_bfloat16* B1 = o1tb + ((size_t)b * C_ + ch) * HW_;
    const __nv_bfloat16* A2 = o2b + ((size_t)b * C_ + ch) * HW_ + mh64 * 128;
    const __nv_bfloat16* B2 = a2b + (size_t)bh * HW_;
    const __nv_bfloat16* S1 = o1b + ((size_t)b * C_ + ch) * HW_;
    const __nv_bfloat16* S2 = o2b + ((size_t)b * C_ + ch) * HW_;

    float acc1[2][4][4], acc2[2][4][4];
#pragma unroll
    for (int mt = 0; mt < 2; mt++)
#pragma unroll
        for (int nt = 0; nt < 4; nt++)
#pragma unroll
            for (int e = 0; e < 4; e++) { acc1[mt][nt][e] = 0.f; acc2[mt][nt][e] = 0.f; }

    const uint32_t sb0 = sbase;
    const uint32_t sb1 = sbase + BPBUF * 4;
    const uint32_t* dA0 = smu;
    const uint32_t* dB0 = smu + BAB_A;
    const uint32_t* dA1 = smu + BPBUF;
    const uint32_t* dB1 = smu + BPBUF + BAB_A;

    BPIPE_STAGE(sb0, A1, B1);
    BPIPE_STAGE(sb1, A1 + 64, B1 + 64);
    CP_WAIT1(); __syncthreads();
    BPIPE_MMA(dA0, dB0, acc1);
    __syncthreads();
    BPIPE_STAGE(sb0, A2, B2);
    CP_WAIT1(); __syncthreads();
    BPIPE_MMA(dA1, dB1, acc1);
    __syncthreads();
    BPIPE_STAGE(sb1, A2 + 64, B2 + 64);
    CP_WAIT1(); __syncthreads();
    BPIPE_MMA(dA0, dB0, acc2);
    CP_WAIT0(); __syncthreads();
    BPIPE_MMA(dA1, dB1, acc2);

    const float gg = 1.f / (1.f + expf(-__ldg(&gate[0])));
    float invy[4], invx[8];
#pragma unroll
    for (int mt = 0; mt < 2; mt++)
#pragma unroll
        for (int half = 0; half < 2; half++) {
            int row = mbase + mt * 16 + g + half * 8;
            invy[mt * 2 + half] =
                1.f / fmaxf(sqrtf(__ldg(&n2h[bh * 128 + mh64 + row])), EPS_);
        }
#pragma unroll
    for (int nt = 0; nt < 4; nt++)
#pragma unroll
        for (int cc = 0; cc < 2; cc++) {
            int col = nbase + nt * 8 + 2 * tig + cc;
            invx[nt * 2 + cc] = 1.f / fmaxf(sqrtf(__ldg(&n1w[bh * 128 + col])), EPS_);
        }

    __nv_bfloat16* fout = fus + ((size_t)b * C_ + ch) * HW_;
#pragma unroll
    for (int mt = 0; mt < 2; mt++)
#pragma unroll
        for (int half = 0; half < 2; half++) {
            int rl = mbase + mt * 16 + g + half * 8;
            int row = mh64 + rl;
            float iy = invy[mt * 2 + half];
#pragma unroll
            for (int nt = 0; nt < 4; nt++) {
                int col = nbase + nt * 8 + 2 * tig;
                float2 s1f = __bfloat1622float2(*(const __nv_bfloat162*)(S1 + row * 128 + col));
                float2 s2f = __bfloat1622float2(*(const __nv_bfloat162*)(S2 + row * 128 + col));
                float ox = gg * (acc1[mt][nt][half * 2 + 0] + s2f.x * iy)
                    + (1.f - gg) * (acc2[mt][nt][half * 2 + 0] + s1f.x * invx[nt * 2 + 0]);
                float oy = gg * (acc1[mt][nt][half * 2 + 1] + s2f.y * iy)
                    + (1.f - gg) * (acc2[mt][nt][half * 2 + 1] + s1f.y * invx[nt * 2 + 1]);
                *(uint32_t*)&fout[row * 128 + col] = f2bf2(ox, oy);
            }
        }
}

// ---------------- host launcher ----------------
extern "C" void kernel_launch(void* const* d_in, const int* in_sizes, int n_in,
                              void* d_out, int out_size)
{
    const float* x1  = (const float*)d_in[0];
    const float* x2  = (const float*)d_in[1];
    const float* Wp  = (const float*)d_in[2];
    const float* bp  = (const float*)d_in[3];
    const float* gate= (const float*)d_in[4];
    const float* pbh = (const float*)d_in[5];
    const float* pbw = (const float*)d_in[6];
    const float* Wm1 = (const float*)d_in[7];
    const float* bm1 = (const float*)d_in[8];
    const float* Wm2 = (const float*)d_in[9];
    const float* bm2 = (const float*)d_in[10];
    float* out = (float*)d_out;

    float *p_n1h, *p_n2h, *p_n1w, *p_n2w;
    __nv_bfloat16 *p_fus, *p_o1b, *p_o2b, *p_o1tb, *p_o2tb, *p_a1b, *p_a2b;
    cudaGetSymbolAddress((void**)&p_fus, g_fus);
    cudaGetSymbolAddress((void**)&p_o1b, g_o1b);
    cudaGetSymbolAddress((void**)&p_o2b, g_o2b);
    cudaGetSymbolAddress((void**)&p_o1tb, g_o1tb);
    cudaGetSymbolAddress((void**)&p_o2tb, g_o2tb);
    cudaGetSymbolAddress((void**)&p_a1b, g_a1b);
    cudaGetSymbolAddress((void**)&p_a2b, g_a2b);
    cudaGetSymbolAddress((void**)&p_n1h, g_n1h);
    cudaGetSymbolAddress((void**)&p_n2h, g_n2h);
    cudaGetSymbolAddress((void**)&p_n1w, g_n1w);
    cudaGetSymbolAddress((void**)&p_n2w, g_n2w);

    cudaFuncSetAttribute(conv_front_kernel, cudaFuncAttributeMaxDynamicSharedMemorySize, SMEM_BYTES);
    cudaFuncSetAttribute(conv3x_kernel, cudaFuncAttributeMaxDynamicSharedMemorySize, C3_SMEM_BYTES);
    cudaFuncSetAttribute(attn_mma_kernel, cudaFuncAttributeMaxDynamicSharedMemorySize, BPIPE_SMEM_BYTES);
    cudaFuncSetAttribute(av_mma_kernel, cudaFuncAttributeMaxDynamicSharedMemorySize, BPIPE_SMEM_BYTES);

    norm_init_kernel<<<32, 256>>>(p_n1h, p_n1w, p_n2h, p_n2w);

    conv_front_kernel<<<dim3(NTILES_, 2), 512, SMEM_BYTES>>>(
        x1, x2, Wp, bp, p_o1b, p_o2b, p_n1h, p_n1w, p_n2h, p_n2w);

    repackT_kernel<<<dim3(4, 2 * C_, B_), 256>>>(p_o1b, p_o2b, p_o1tb, p_o2tb);

    attn_mma_kernel<<<dim3(B_ * HEADS_, 2, 2), 256, BPIPE_SMEM_BYTES>>>(
        p_o1b, p_o2b, p_o1tb, p_o2tb, p_n1h, p_n2h, p_n1w, p_n2w, pbh, pbw, p_a1b, p_a2b);

    av_mma_kernel<<<dim3(C_, B_, 2), 256, BPIPE_SMEM_BYTES>>>(
        p_o1b, p_o2b, p_o1tb, p_a1b, p_a2b, p_n2h, p_n1w, gate, p_fus);

    conv3x_kernel<<<NTILES_, 512, C3_SMEM_BYTES>>>(p_fus, Wp, bp, Wm1, bm1, Wm2, bm2,
                                                   x1, x2, out);

    (void)in_sizes; (void)n_in; (void)out_size;
}